// round 12
// baseline (speedup 1.0000x reference)
#include <cuda_runtime.h>
#include <cstdint>
#include <math.h>

#define TSTEPS 4096
#define DIN    512
#define FDIM   256
#define HID    200
#define G4     800
#define KDIM   40
#define NSLOT  128
#define EPSF   1e-12f
#define CLSZ   8

// ---------------- scratch (device globals) ----------------
__device__ float g_xs[TSTEPS * FDIM];
__device__ float g_gx[TSTEPS * G4];
__device__ float g_WinT[FDIM * DIN];
__device__ float g_Wx[G4 * FDIM];
__device__ float g_wy[G4];
__device__ float g_bsum[G4];
__device__ float g_WkT[KDIM * HID];   // W_k transposed: [40][200]

// ---------------- helpers ----------------
__device__ __forceinline__ float fsigmoid(float x) {
    return __fdividef(1.f, 1.f + __expf(-x));
}
__device__ __forceinline__ float ftanh(float x) {
    float a = fabsf(x);
    float e = __expf(-2.f * a);
    float r = __fdividef(1.f - e, 1.f + e);
    return copysignf(r, x);
}
__device__ __forceinline__ uint32_t smem_u32(const void* p) {
    return (uint32_t)__cvta_generic_to_shared(p);
}
__device__ __forceinline__ uint32_t my_cluster_rank() {
    uint32_t r; asm("mov.u32 %0, %%cluster_ctarank;" : "=r"(r)); return r;
}
__device__ __forceinline__ uint32_t mapa_u32(uint32_t laddr, uint32_t rank) {
    uint32_t r;
    asm("mapa.shared::cluster.u32 %0, %1, %2;" : "=r"(r) : "r"(laddr), "r"(rank));
    return r;
}
__device__ __forceinline__ void cluster_arrive_() {
    asm volatile("barrier.cluster.arrive.aligned;" ::: "memory");
}
__device__ __forceinline__ void cluster_wait_() {
    asm volatile("barrier.cluster.wait.aligned;" ::: "memory");
}
__device__ __forceinline__ void cluster_sync_() {
    cluster_arrive_(); cluster_wait_();
}
__device__ __forceinline__ void dsmem_st_u64(uint32_t raddr, unsigned long long v) {
    asm volatile("st.shared::cluster.u64 [%0], %1;" :: "r"(raddr), "l"(v) : "memory");
}
__device__ __forceinline__ void bar_sync_(int id, int cnt) {
    asm volatile("bar.sync %0, %1;" :: "r"(id), "r"(cnt) : "memory");
}
// 16B vector load from shared (LDS.128) into two u64
__device__ __forceinline__ void lds128(unsigned long long& x, unsigned long long& y, uint32_t addr) {
    asm volatile("ld.shared.v2.u64 {%0, %1}, [%2];" : "=l"(x), "=l"(y) : "r"(addr));
}
// packed fp32x2 FMA: d = a*b + d  (sm_100 FFMA2; ptxas never auto-fuses this)
__device__ __forceinline__ void fma2(unsigned long long& d, unsigned long long a, unsigned long long b) {
    asm("fma.rn.f32x2 %0, %1, %2, %0;" : "+l"(d) : "l"(a), "l"(b));
}
__device__ __forceinline__ float2 unpack2(unsigned long long v) {
    float2 r; asm("mov.b64 {%0, %1}, %2;" : "=f"(r.x), "=f"(r.y) : "l"(v)); return r;
}
__device__ __forceinline__ unsigned long long pack2(float x, float y) {
    unsigned long long v; asm("mov.b64 %0, {%1, %2};" : "=l"(v) : "f"(x), "f"(y)); return v;
}

// ---------------- prep ----------------
__global__ void prep_kernel(const float* __restrict__ W_in, const float* __restrict__ W_ih,
                            const float* __restrict__ b_ih, const float* __restrict__ b_hh,
                            const float* __restrict__ W_k) {
    int idx = blockIdx.x * blockDim.x + threadIdx.x;
    if (idx < G4 * FDIM) {
        int n = idx / FDIM, k = idx % FDIM;
        g_Wx[idx] = W_ih[n * (FDIM + 1) + k];
    }
    if (idx < DIN * FDIM) {
        int k = idx / FDIM, n = idx % FDIM;
        g_WinT[n * DIN + k] = W_in[idx];
    }
    if (idx < G4) {
        g_wy[idx]   = W_ih[idx * (FDIM + 1) + FDIM];
        g_bsum[idx] = b_ih[idx] + b_hh[idx];
    }
    if (idx < KDIM * HID) {
        int k = idx / HID, h = idx % HID;
        g_WkT[idx] = W_k[h * KDIM + k];
    }
}

// ---------------- GEMM C = A * B^T ----------------
__device__ __forceinline__ void gemm_nt_body(
    const float* __restrict__ A, const float* __restrict__ B, float* __restrict__ C,
    int M, int N, int K,
    const float* __restrict__ bias, const float* __restrict__ yvec, const float* __restrict__ wy)
{
    __shared__ __align__(16) float As[16][64];
    __shared__ __align__(16) float Bs[16][64];
    const int m0 = blockIdx.y * 64, n0 = blockIdx.x * 64;
    const int tid = threadIdx.x;
    const int tx = tid % 16, ty = tid / 16;
    const int lr = tid / 4, lc4 = (tid % 4) * 4;

    float acc[4][4];
#pragma unroll
    for (int i = 0; i < 4; i++)
#pragma unroll
        for (int j = 0; j < 4; j++) acc[i][j] = 0.f;

    for (int k0 = 0; k0 < K; k0 += 16) {
        float4 av = *reinterpret_cast<const float4*>(A + (size_t)(m0 + lr) * K + k0 + lc4);
        As[lc4 + 0][lr] = av.x; As[lc4 + 1][lr] = av.y;
        As[lc4 + 2][lr] = av.z; As[lc4 + 3][lr] = av.w;
        float4 bv = make_float4(0.f, 0.f, 0.f, 0.f);
        if (n0 + lr < N) bv = *reinterpret_cast<const float4*>(B + (size_t)(n0 + lr) * K + k0 + lc4);
        Bs[lc4 + 0][lr] = bv.x; Bs[lc4 + 1][lr] = bv.y;
        Bs[lc4 + 2][lr] = bv.z; Bs[lc4 + 3][lr] = bv.w;
        __syncthreads();
#pragma unroll
        for (int kk = 0; kk < 16; kk++) {
            float4 a4 = *reinterpret_cast<const float4*>(&As[kk][ty * 4]);
            float4 b4 = *reinterpret_cast<const float4*>(&Bs[kk][tx * 4]);
            float aa[4] = {a4.x, a4.y, a4.z, a4.w};
            float bb[4] = {b4.x, b4.y, b4.z, b4.w};
#pragma unroll
            for (int i = 0; i < 4; i++)
#pragma unroll
                for (int j = 0; j < 4; j++) acc[i][j] = fmaf(aa[i], bb[j], acc[i][j]);
        }
        __syncthreads();
    }
#pragma unroll
    for (int i = 0; i < 4; i++) {
        int m = m0 + ty * 4 + i;
        float yv = 0.f;
        if (yvec) yv = (m == 0) ? 0.f : yvec[m - 1];
#pragma unroll
        for (int j = 0; j < 4; j++) {
            int n = n0 + tx * 4 + j;
            if (n < N) {
                float v = acc[i][j] + (bias ? bias[n] : 0.f);
                if (wy) v = fmaf(yv, wy[n], v);
                C[(size_t)m * N + n] = v;
            }
        }
    }
}

__global__ void __launch_bounds__(256) gemm1_kernel(const float* __restrict__ x,
                                                    const float* __restrict__ b_in) {
    gemm_nt_body(x, g_WinT, g_xs, TSTEPS, FDIM, DIN, b_in, nullptr, nullptr);
}
__global__ void __launch_bounds__(256) gemm2_kernel(const float* __restrict__ y) {
    gemm_nt_body(g_xs, g_Wx, g_gx, TSTEPS, G4, FDIM, g_bsum, y, g_wy);
}

// ---------------- fused kernel shared state ----------------
struct Shm {
    __align__(16) float h[2][HID];          // double-buffered hidden (dsmem broadcast target)
    __align__(8)  float Ws[HID];
    __align__(8)  float bk[KDIM];
    __align__(16) float key[4][KDIM];       // quad-buffered (keys pipeline vs shadow-MANN)
    __align__(16) float kn[4][KDIM];
    float sig[4];
    float wsum[4];
    float bs;
};

// MANN step on buffer kb (threads 0..127 only; named barrier 1, incl. trailing
// bar to protect wsum reuse across iterations — runs in cluster-barrier shadow)
__device__ __forceinline__ void mann_step(Shm& S, int tid, int kb,
                                          unsigned long long* M2, float& wr)
{
    const float sg = S.sig[kb];
    const float ww = fmaf(sg, wr, 1.f - sg);        // wlu mask == 1 identically
    const unsigned long long ww2 = pack2(ww, ww);
    const uint32_t kaddr  = smem_u32(&S.key[kb][0]);
    const uint32_t knaddr = smem_u32(&S.kn[kb][0]);
    unsigned long long n0 = 0, n1 = 0, d0 = 0, d1 = 0;
#pragma unroll
    for (int q = 0; q < 20; q += 2) {
        unsigned long long k0, k1, kn0, kn1;
        lds128(k0,  k1,  kaddr  + (uint32_t)q * 8u);
        lds128(kn0, kn1, knaddr + (uint32_t)q * 8u);
        fma2(M2[q],     ww2, k0);
        fma2(M2[q + 1], ww2, k1);
        fma2(n0, M2[q],     M2[q]);
        fma2(n1, M2[q + 1], M2[q + 1]);
        fma2(d0, M2[q],     kn0);
        fma2(d1, M2[q + 1], kn1);
    }
    float2 na = unpack2(n0), nb = unpack2(n1), da = unpack2(d0), db = unpack2(d1);
    float ns  = (na.x + na.y) + (nb.x + nb.y);      // >= 4e-11, never 0
    float dot = (da.x + da.y) + (db.x + db.y);
    float e = __expf(dot * rsqrtf(ns));             // |logit| <= sqrt(40)
    float acc = e;
#pragma unroll
    for (int off = 16; off > 0; off >>= 1) acc += __shfl_xor_sync(0xffffffffu, acc, off);
    if ((tid & 31) == 0) S.wsum[tid >> 5] = acc;
    bar_sync_(1, 128);
    float tot = (S.wsum[0] + S.wsum[1]) + (S.wsum[2] + S.wsum[3]);
    wr = __fdividef(e, tot);
    bar_sync_(1, 128);                              // wsum reads done before next step's writes
}

// keys + sigma from hidden vector hb into buffer kb (threads 128..215)
__device__ __forceinline__ void keys_sigma(Shm& S, int tid, const float* __restrict__ hb, int kb,
                                           const unsigned long long* wk)
{
    if (tid < 208) {                 // keys: 2 threads per output (tid 128..207)
        const int k = (tid - 128) >> 1, half = (tid - 128) & 1;
        const unsigned mask = (tid < 192) ? 0xffffffffu : 0x0000FFFFu;
        const uint32_t haddr = smem_u32(hb) + (uint32_t)half * 400u;
        unsigned long long a0 = 0, a1 = 0, a2 = 0, a3 = 0;
#pragma unroll
        for (int q = 0; q < 25; q++) {
            unsigned long long x, y;
            lds128(x, y, haddr + (uint32_t)q * 16u);
            if (q & 1) { fma2(a2, wk[2 * q], x); fma2(a3, wk[2 * q + 1], y); }
            else       { fma2(a0, wk[2 * q], x); fma2(a1, wk[2 * q + 1], y); }
        }
        float2 xa = unpack2(a0), xb = unpack2(a1), xc = unpack2(a2), xd = unpack2(a3);
        float acc = ((xa.x + xa.y) + (xb.x + xb.y)) + ((xc.x + xc.y) + (xd.x + xd.y));
        acc += __shfl_xor_sync(mask, acc, 1);
        if (half == 0) {
            float kv = ftanh(acc + S.bk[k]);
            S.key[kb][k] = kv;
            S.kn[kb][k]  = kv / fmaxf(fabsf(kv), EPSF);
        }
    } else if (tid < 216) {          // sigma: 8 threads (warp 6 lanes 16..23)
        const int p = tid - 208;
        float a = 0.f;
#pragma unroll
        for (int i = 0; i < 25; i++) a = fmaf(hb[p * 25 + i], S.Ws[p * 25 + i], a);
        a += __shfl_xor_sync(0x00FF0000u, a, 4);
        a += __shfl_xor_sync(0x00FF0000u, a, 2);
        a += __shfl_xor_sync(0x00FF0000u, a, 1);
        if (p == 0) S.sig[kb] = fsigmoid(a + S.bs);
    }
}

__global__ void __cluster_dims__(CLSZ, 1, 1) __launch_bounds__(256, 1)
fused_kernel(const float* __restrict__ W_hh,
             const float* __restrict__ b_k,
             const float* __restrict__ W_s, const float* __restrict__ b_s,
             float* __restrict__ out)
{
    __shared__ Shm S;
    const int tid = threadIdx.x;
    const uint32_t rank = my_cluster_rank();
    const bool is_consumer = (rank == CLSZ - 1);

    if (tid < HID) { S.h[0][tid] = 0.f; S.h[1][tid] = 0.f; }

    if (!is_consumer) {
        // ================= LSTM producer =================
        // units 30,30,30,30,30,30,20 (even bases for paired u64 h-stores)
        const int units = (rank < 6) ? 30 : 20;
        const int base  = 30 * (int)rank;            // rank 6 -> 180
        const int nact  = 8 * units;                 // 240 / 160
        const bool act  = tid < nact;
        const int u   = tid >> 3;                    // unit within CTA
        const int sub = tid & 7;                     // 2*gate + cc
        const int g   = sub >> 1;
        const int cc  = sub & 1;
        const int grow = act ? (g * HID + base + u) : 0;

        unsigned long long w[50];
        if (act) {
            const unsigned long long* wp =
                reinterpret_cast<const unsigned long long*>(W_hh + (size_t)grow * HID + cc * 100);
#pragma unroll
            for (int q = 0; q < 50; q++) w[q] = wp[q];
        }
        unsigned mask = 0;
        if (act) {
            int rem = nact - (tid & ~31);
            mask = (rem >= 32) ? 0xffffffffu : ((1u << rem) - 1u);
        }
        const unsigned submask = mask & 0x01010101u;  // sub==0 lanes of this warp
        uint32_t r_h[CLSZ];
        if (act && sub == 0) {
            uint32_t hA = smem_u32(&S.h[0][0]);
#pragma unroll
            for (int p = 0; p < CLSZ; p++) r_h[p] = mapa_u32(hA, (uint32_t)p);
        }

        __syncthreads();
        cluster_sync_();   // h zeroed everywhere before any traffic

        float cst = 0.f;
        float gxv = (act && cc == 0) ? g_gx[grow] : 0.f;

        for (int t = 0; t < TSTEPS; t++) {
            const int buf = t & 1, bw = buf ^ 1;
            if (act) {
                const uint32_t haddr = smem_u32(&S.h[buf][0]) + (uint32_t)cc * 400u;
                unsigned long long a0 = 0, a1 = 0, a2 = 0, a3 = 0;
#pragma unroll
                for (int q = 0; q < 25; q++) {
                    unsigned long long x, y;
                    lds128(x, y, haddr + (uint32_t)q * 16u);
                    if (q & 1) { fma2(a2, w[2 * q], x); fma2(a3, w[2 * q + 1], y); }
                    else       { fma2(a0, w[2 * q], x); fma2(a1, w[2 * q + 1], y); }
                }
                float2 f0 = unpack2(a0), f1 = unpack2(a1), f2 = unpack2(a2), f3 = unpack2(a3);
                float dsum = ((f0.x + f0.y) + (f1.x + f1.y)) + ((f2.x + f2.y) + (f3.x + f3.y));
                dsum += __shfl_xor_sync(mask, dsum, 1);          // combine k-halves
                float av = 0.f;
                if (cc == 0) {
                    float gs = dsum + gxv;
                    av = (g == 2) ? ftanh(gs) : fsigmoid(gs);    // gate activation (even lanes)
                }
                float fv = __shfl_down_sync(mask, av, 2);
                float gv = __shfl_down_sync(mask, av, 4);
                float ov = __shfl_down_sync(mask, av, 6);
                if (sub == 0) {
                    cst = fv * cst + av * gv;
                    float h = ov * ftanh(cst);
                    float hhi = __shfl_down_sync(submask, h, 8); // partner unit u+1
                    if ((u & 1) == 0) {
                        const unsigned long long hv = pack2(h, hhi);
                        const uint32_t off = (uint32_t)(bw * HID + base + u) * 4u;
#pragma unroll
                        for (int p = 0; p < CLSZ; p++) dsmem_st_u64(r_h[p] + off, hv);
                    }
                }
            }
            cluster_arrive_();                   // release h_{t+1} stores
            // prefetch next gx in the barrier shadow
            float gxn = 0.f;
            if (act && cc == 0) {
                int tn = (t + 1 < TSTEPS) ? (t + 1) : t;
                gxn = g_gx[(size_t)tn * G4 + grow];
            }
            cluster_wait_();                     // acquire for next step's reads
            gxv = gxn;
        }
        return;
    }

    // ================= consumer CTA =================
    unsigned long long wk[50];       // keys threads: WkT slice in registers
    if (tid >= 128 && tid < 208) {
        const int k = (tid - 128) >> 1, half = (tid - 128) & 1;
        const unsigned long long* wp =
            reinterpret_cast<const unsigned long long*>(g_WkT + k * HID + half * 100);
#pragma unroll
        for (int q = 0; q < 50; q++) wk[q] = wp[q];
    }
    unsigned long long M2[20];
    float wr = 0.f;
    for (int i = tid; i < HID; i += 256) S.Ws[i] = W_s[i];
    if (tid < KDIM) S.bk[tid] = b_k[tid];
    if (tid == 0)   S.bs = b_s[0];
    if (tid < NSLOT) {
#pragma unroll
        for (int q = 0; q < 20; q++) M2[q] = pack2(1e-6f, 1e-6f);
        wr = (tid == 0) ? 1.f : 0.f;
    }

    __syncthreads();
    cluster_sync_();   // h zeroed everywhere before any traffic

    for (int t = 0; t < TSTEPS; t++) {
        // keys(h_t) on warps 4-7, on the cluster critical path
        if (tid >= 128 && t >= 1) keys_sigma(S, tid, &S.h[t & 1][0], t & 3, wk);
        cluster_arrive_();
        // MANN for key buffer (t-1)&3 in the barrier shadow (warps 0-3)
        if (tid < 128 && t >= 2) mann_step(S, tid, (t - 1) & 3, M2, wr);
        cluster_wait_();
    }

    // tail 1: keys for hiddens[4095] (h_4096, buffer 0) -> key[0] || MANN for key[4095&3=3]
    if (tid >= 128) keys_sigma(S, tid, &S.h[0][0], 0, wk);
    else            mann_step(S, tid, 3, M2, wr);
    __syncthreads();
    // tail 2: MANN for key[0]
    if (tid < 128)  mann_step(S, tid, 0, M2, wr);

    if (tid < NSLOT) {
#pragma unroll
        for (int q = 0; q < 20; q++) {
            float2 v = unpack2(M2[q]);
            out[tid * KDIM + 2 * q]     = v.x;
            out[tid * KDIM + 2 * q + 1] = v.y;
        }
    }
}

// ---------------- launch ----------------
extern "C" void kernel_launch(void* const* d_in, const int* in_sizes, int n_in,
                              void* d_out, int out_size) {
    const float* x    = (const float*)d_in[0];
    const float* y    = (const float*)d_in[1];
    const float* W_in = (const float*)d_in[2];
    const float* b_in = (const float*)d_in[3];
    const float* W_ih = (const float*)d_in[4];
    const float* W_hh = (const float*)d_in[5];
    const float* b_ih = (const float*)d_in[6];
    const float* b_hh = (const float*)d_in[7];
    const float* W_k  = (const float*)d_in[8];
    const float* b_k  = (const float*)d_in[9];
    const float* W_s  = (const float*)d_in[10];
    const float* b_s  = (const float*)d_in[11];
    // gamma (d_in[12]) provably unused: wlu mask is identically 1, wu/gamma cancel

    prep_kernel<<<(G4 * FDIM + 255) / 256, 256>>>(W_in, W_ih, b_ih, b_hh, W_k);
    gemm1_kernel<<<dim3(FDIM / 64, TSTEPS / 64), 256>>>(x, b_in);
    gemm2_kernel<<<dim3((G4 + 63) / 64, TSTEPS / 64), 256>>>(y);
    fused_kernel<<<CLSZ, 256>>>(W_hh, b_k, W_s, b_s, (float*)d_out);
}

// round 13
// speedup vs baseline: 1.1046x; 1.1046x over previous
#include <cuda_runtime.h>
#include <cstdint>
#include <math.h>

#define TSTEPS 4096
#define DIN    512
#define FDIM   256
#define HID    200
#define G4     800
#define KDIM   40
#define NSLOT  128
#define EPSF   1e-12f
#define CLSZ   8
#define NWORK  128          // worker CTAs (grid = 8 + 128 = 136 = 17 clusters)

// ---------------- scratch (device globals) ----------------
__device__ float g_xs[TSTEPS * FDIM];
__device__ float g_gx[TSTEPS * G4];
__device__ float g_WinT[FDIM * DIN];
__device__ float g_Wx[G4 * FDIM];
__device__ float g_wy[G4];
__device__ float g_bsum[G4];
__device__ float g_WkT[KDIM * HID];      // W_k transposed: [40][200]
__device__ unsigned g_prog1[64];         // xs m-block tile counters (target 4)
__device__ unsigned g_prog2[64];         // gx m-block tile counters (target 13)

// ---------------- helpers ----------------
__device__ __forceinline__ float fsigmoid(float x) {
    return __fdividef(1.f, 1.f + __expf(-x));
}
__device__ __forceinline__ float ftanh(float x) {
    float a = fabsf(x);
    float e = __expf(-2.f * a);
    float r = __fdividef(1.f - e, 1.f + e);
    return copysignf(r, x);
}
__device__ __forceinline__ uint32_t smem_u32(const void* p) {
    return (uint32_t)__cvta_generic_to_shared(p);
}
__device__ __forceinline__ uint32_t my_cluster_rank() {
    uint32_t r; asm("mov.u32 %0, %%cluster_ctarank;" : "=r"(r)); return r;
}
__device__ __forceinline__ uint32_t mapa_u32(uint32_t laddr, uint32_t rank) {
    uint32_t r;
    asm("mapa.shared::cluster.u32 %0, %1, %2;" : "=r"(r) : "r"(laddr), "r"(rank));
    return r;
}
__device__ __forceinline__ void cluster_sync_() {
    asm volatile("barrier.cluster.arrive.aligned;" ::: "memory");
    asm volatile("barrier.cluster.wait.aligned;" ::: "memory");
}
__device__ __forceinline__ void dsmem_st_f32(uint32_t raddr, float v) {
    asm volatile("st.shared::cluster.f32 [%0], %1;" :: "r"(raddr), "f"(v) : "memory");
}
__device__ __forceinline__ void bar_sync_(int id, int cnt) {
    asm volatile("bar.sync %0, %1;" :: "r"(id), "r"(cnt) : "memory");
}
// acquire-poll a GPU-scope progress counter until it reaches target
__device__ __forceinline__ void wait_prog(const unsigned* p, unsigned target) {
    unsigned v;
    do {
        asm volatile("ld.acquire.gpu.u32 %0, [%1];" : "=r"(v) : "l"(p) : "memory");
    } while (v < target);
}
// 16B vector load from shared (LDS.128) into two u64
__device__ __forceinline__ void lds128(unsigned long long& x, unsigned long long& y, uint32_t addr) {
    asm volatile("ld.shared.v2.u64 {%0, %1}, [%2];" : "=l"(x), "=l"(y) : "r"(addr));
}
// packed fp32x2 FMA: d = a*b + d  (sm_100 FFMA2; ptxas never auto-fuses this)
__device__ __forceinline__ void fma2(unsigned long long& d, unsigned long long a, unsigned long long b) {
    asm("fma.rn.f32x2 %0, %1, %2, %0;" : "+l"(d) : "l"(a), "l"(b));
}
__device__ __forceinline__ float2 unpack2(unsigned long long v) {
    float2 r; asm("mov.b64 {%0, %1}, %2;" : "=f"(r.x), "=f"(r.y) : "l"(v)); return r;
}
__device__ __forceinline__ unsigned long long pack2(float x, float y) {
    unsigned long long v; asm("mov.b64 %0, {%1, %2};" : "=l"(v) : "f"(x), "f"(y)); return v;
}

// ---------------- prep ----------------
__global__ void prep_kernel(const float* __restrict__ W_in, const float* __restrict__ W_ih,
                            const float* __restrict__ b_ih, const float* __restrict__ b_hh,
                            const float* __restrict__ W_k) {
    int idx = blockIdx.x * blockDim.x + threadIdx.x;
    if (idx < G4 * FDIM) {
        int n = idx / FDIM, k = idx % FDIM;
        g_Wx[idx] = W_ih[n * (FDIM + 1) + k];
    }
    if (idx < DIN * FDIM) {
        int k = idx / FDIM, n = idx % FDIM;
        g_WinT[n * DIN + k] = W_in[idx];
    }
    if (idx < G4) {
        g_wy[idx]   = W_ih[idx * (FDIM + 1) + FDIM];
        g_bsum[idx] = b_ih[idx] + b_hh[idx];
    }
    if (idx < KDIM * HID) {
        int k = idx / HID, h = idx % HID;
        g_WkT[idx] = W_k[h * KDIM + k];
    }
    if (idx < 64) { g_prog1[idx] = 0; g_prog2[idx] = 0; }   // reset every graph replay
}

// ---------------- one 64x64 GEMM tile: C = A * B^T (+bias +y-term) ----------------
__device__ void gemm_tile(
    const float* __restrict__ A, const float* __restrict__ B, float* __restrict__ C,
    int N, int K,
    const float* __restrict__ bias, const float* __restrict__ yvec, const float* __restrict__ wy,
    int m0, int n0)
{
    __shared__ __align__(16) float As[16][64];
    __shared__ __align__(16) float Bs[16][64];
    const int tid = threadIdx.x;
    const int tx = tid % 16, ty = tid / 16;
    const int lr = tid / 4, lc4 = (tid % 4) * 4;

    float acc[4][4];
#pragma unroll
    for (int i = 0; i < 4; i++)
#pragma unroll
        for (int j = 0; j < 4; j++) acc[i][j] = 0.f;

    for (int k0 = 0; k0 < K; k0 += 16) {
        float4 av = *reinterpret_cast<const float4*>(A + (size_t)(m0 + lr) * K + k0 + lc4);
        As[lc4 + 0][lr] = av.x; As[lc4 + 1][lr] = av.y;
        As[lc4 + 2][lr] = av.z; As[lc4 + 3][lr] = av.w;
        float4 bv = make_float4(0.f, 0.f, 0.f, 0.f);
        if (n0 + lr < N) bv = *reinterpret_cast<const float4*>(B + (size_t)(n0 + lr) * K + k0 + lc4);
        Bs[lc4 + 0][lr] = bv.x; Bs[lc4 + 1][lr] = bv.y;
        Bs[lc4 + 2][lr] = bv.z; Bs[lc4 + 3][lr] = bv.w;
        __syncthreads();
#pragma unroll
        for (int kk = 0; kk < 16; kk++) {
            float4 a4 = *reinterpret_cast<const float4*>(&As[kk][ty * 4]);
            float4 b4 = *reinterpret_cast<const float4*>(&Bs[kk][tx * 4]);
            float aa[4] = {a4.x, a4.y, a4.z, a4.w};
            float bb[4] = {b4.x, b4.y, b4.z, b4.w};
#pragma unroll
            for (int i = 0; i < 4; i++)
#pragma unroll
                for (int j = 0; j < 4; j++) acc[i][j] = fmaf(aa[i], bb[j], acc[i][j]);
        }
        __syncthreads();
    }
#pragma unroll
    for (int i = 0; i < 4; i++) {
        int m = m0 + ty * 4 + i;
        float yv = 0.f;
        if (yvec) yv = (m == 0) ? 0.f : yvec[m - 1];
#pragma unroll
        for (int j = 0; j < 4; j++) {
            int n = n0 + tx * 4 + j;
            if (n < N) {
                float v = acc[i][j] + (bias ? bias[n] : 0.f);
                if (wy) v = fmaf(yv, wy[n], v);
                C[(size_t)m * N + n] = v;
            }
        }
    }
}

// ---------------- fused kernel shared state ----------------
struct Shm {
    __align__(16) float h[2][HID];          // double-buffered hidden (dsmem broadcast target)
    __align__(8)  float Ws[HID];
    __align__(8)  float bk[KDIM];
    __align__(16) float key[2][KDIM];       // double-buffered (keys pipeline vs MANN)
    __align__(16) float kn[2][KDIM];
    float sig[2];
    float wsum[4];
    float bs;
};

// MANN step on buffer kb (threads 0..127 only; uses named barrier 1)
__device__ __forceinline__ void mann_step(Shm& S, int tid, int kb,
                                          unsigned long long* M2, float& wr)
{
    const float sg = S.sig[kb];
    const float ww = fmaf(sg, wr, 1.f - sg);        // wlu mask == 1 identically
    const unsigned long long ww2 = pack2(ww, ww);
    const uint32_t kaddr  = smem_u32(&S.key[kb][0]);
    const uint32_t knaddr = smem_u32(&S.kn[kb][0]);
    unsigned long long n0 = 0, n1 = 0, d0 = 0, d1 = 0;
#pragma unroll
    for (int q = 0; q < 20; q += 2) {
        unsigned long long k0, k1, kn0, kn1;
        lds128(k0,  k1,  kaddr  + (uint32_t)q * 8u);
        lds128(kn0, kn1, knaddr + (uint32_t)q * 8u);
        fma2(M2[q],     ww2, k0);
        fma2(M2[q + 1], ww2, k1);
        fma2(n0, M2[q],     M2[q]);
        fma2(n1, M2[q + 1], M2[q + 1]);
        fma2(d0, M2[q],     kn0);
        fma2(d1, M2[q + 1], kn1);
    }
    float2 na = unpack2(n0), nb = unpack2(n1), da = unpack2(d0), db = unpack2(d1);
    float ns  = (na.x + na.y) + (nb.x + nb.y);      // >= 4e-11, never 0
    float dot = (da.x + da.y) + (db.x + db.y);
    float e = __expf(dot * rsqrtf(ns));             // |logit| <= sqrt(40)
    float acc = e;
#pragma unroll
    for (int off = 16; off > 0; off >>= 1) acc += __shfl_xor_sync(0xffffffffu, acc, off);
    if ((tid & 31) == 0) S.wsum[tid >> 5] = acc;
    bar_sync_(1, 128);                              // MANN group only
    float tot = (S.wsum[0] + S.wsum[1]) + (S.wsum[2] + S.wsum[3]);
    wr = __fdividef(e, tot);
}

// keys + sigma from hidden vector hb into buffer kb (threads 128..215)
__device__ __forceinline__ void keys_sigma(Shm& S, int tid, const float* __restrict__ hb, int kb,
                                           const unsigned long long* wk)
{
    if (tid < 208) {                 // keys: 2 threads per output (tid 128..207)
        const int k = (tid - 128) >> 1, half = (tid - 128) & 1;
        const unsigned mask = (tid < 192) ? 0xffffffffu : 0x0000FFFFu;
        const uint32_t haddr = smem_u32(hb) + (uint32_t)half * 400u;
        unsigned long long a0 = 0, a1 = 0, a2 = 0, a3 = 0;
#pragma unroll
        for (int q = 0; q < 25; q++) {
            unsigned long long x, y;
            lds128(x, y, haddr + (uint32_t)q * 16u);
            if (q & 1) { fma2(a2, wk[2 * q], x); fma2(a3, wk[2 * q + 1], y); }
            else       { fma2(a0, wk[2 * q], x); fma2(a1, wk[2 * q + 1], y); }
        }
        float2 xa = unpack2(a0), xb = unpack2(a1), xc = unpack2(a2), xd = unpack2(a3);
        float acc = ((xa.x + xa.y) + (xb.x + xb.y)) + ((xc.x + xc.y) + (xd.x + xd.y));
        acc += __shfl_xor_sync(mask, acc, 1);
        if (half == 0) {
            float kv = ftanh(acc + S.bk[k]);
            S.key[kb][k] = kv;
            S.kn[kb][k]  = kv / fmaxf(fabsf(kv), EPSF);
        }
    } else if (tid < 216) {          // sigma: 8 threads (warp 6 lanes 16..23)
        const int p = tid - 208;
        float a = 0.f;
#pragma unroll
        for (int i = 0; i < 25; i++) a = fmaf(hb[p * 25 + i], S.Ws[p * 25 + i], a);
        a += __shfl_xor_sync(0x00FF0000u, a, 4);
        a += __shfl_xor_sync(0x00FF0000u, a, 2);
        a += __shfl_xor_sync(0x00FF0000u, a, 1);
        if (p == 0) S.sig[kb] = fsigmoid(a + S.bs);
    }
}

__global__ void __cluster_dims__(CLSZ, 1, 1) __launch_bounds__(256, 1)
fused_kernel(const float* __restrict__ W_hh,
             const float* __restrict__ b_k,
             const float* __restrict__ W_s, const float* __restrict__ b_s,
             const float* __restrict__ x, const float* __restrict__ b_in,
             const float* __restrict__ y,
             float* __restrict__ out)
{
    __shared__ Shm S;
    const int tid = threadIdx.x;

    // ================= worker CTAs: GEMMs overlapped with the scan =================
    if (blockIdx.x >= CLSZ) {
        const int wkr = blockIdx.x - CLSZ;    // 0..NWORK-1
        // phase 1: xs tiles (64 mb x 4 nb), mb-major so low-t blocks finish first
        for (int tile = wkr; tile < 64 * 4; tile += NWORK) {
            const int mb = tile >> 2, nb = tile & 3;
            gemm_tile(x, g_WinT, g_xs, FDIM, DIN, b_in, nullptr, nullptr, mb * 64, nb * 64);
            __threadfence();
            __syncthreads();
            if (tid == 0) atomicAdd(&g_prog1[mb], 1u);
        }
        // phase 2: gx tiles (64 mb x 13 nb), gated on the xs m-block
        for (int tile = wkr; tile < 64 * 13; tile += NWORK) {
            const int mb = tile / 13, nb = tile % 13;
            if (tid == 0) wait_prog(&g_prog1[mb], 4u);
            __syncthreads();
            gemm_tile(g_xs, g_Wx, g_gx, G4, FDIM, g_bsum, y, g_wy, mb * 64, nb * 64);
            __threadfence();
            __syncthreads();
            if (tid == 0) atomicAdd(&g_prog2[mb], 1u);
        }
        return;
    }

    // ================= scan cluster (CTAs 0..7) — R11-identical =================
    const uint32_t rank = my_cluster_rank();
    const bool is_consumer = (rank == CLSZ - 1);

    if (tid < HID) { S.h[0][tid] = 0.f; S.h[1][tid] = 0.f; }

    if (!is_consumer) {
        // ---------------- LSTM producer ----------------
        const int units = (rank < 6) ? 29 : 26;
        const int base  = 29 * (int)rank;            // rank 6 -> 174
        const int nact  = 8 * units;
        const bool act  = tid < nact;
        const int u   = tid >> 3;                    // unit within CTA
        const int sub = tid & 7;                     // 2*gate + cc
        const int g   = sub >> 1;
        const int cc  = sub & 1;
        const int grow = act ? (g * HID + base + u) : 0;

        unsigned long long w[50];
        if (act) {
            const unsigned long long* wp =
                reinterpret_cast<const unsigned long long*>(W_hh + (size_t)grow * HID + cc * 100);
#pragma unroll
            for (int q = 0; q < 50; q++) w[q] = wp[q];
        }
        unsigned mask = 0;
        if (act) {
            int rem = nact - (tid & ~31);
            mask = (rem >= 32) ? 0xffffffffu : ((1u << rem) - 1u);
        }
        uint32_t r_h[CLSZ];
        if (act && sub == 0) {
            uint32_t hA = smem_u32(&S.h[0][0]);
#pragma unroll
            for (int p = 0; p < CLSZ; p++) r_h[p] = mapa_u32(hA, (uint32_t)p);
        }

        __syncthreads();
        cluster_sync_();   // h zeroed everywhere before any traffic

        float cst = 0.f;
        float gxv = 0.f;
        if (act && cc == 0) {
            wait_prog(&g_prog2[0], 13u);             // first gx m-block ready
            gxv = g_gx[grow];
        }

        for (int t = 0; t < TSTEPS; t++) {
            const int buf = t & 1, bw = buf ^ 1;
            float gxn = 0.f;
            if (act && cc == 0) {
                int tn = (t + 1 < TSTEPS) ? (t + 1) : t;   // prefetch next gx
                if ((tn & 63) == 0 && tn != t) wait_prog(&g_prog2[tn >> 6], 13u);
                gxn = g_gx[(size_t)tn * G4 + grow];
            }
            if (act) {
                const uint32_t haddr = smem_u32(&S.h[buf][0]) + (uint32_t)cc * 400u;
                unsigned long long a0 = 0, a1 = 0, a2 = 0, a3 = 0;
#pragma unroll
                for (int q = 0; q < 25; q++) {
                    unsigned long long xv, yv;
                    lds128(xv, yv, haddr + (uint32_t)q * 16u);
                    if (q & 1) { fma2(a2, w[2 * q], xv); fma2(a3, w[2 * q + 1], yv); }
                    else       { fma2(a0, w[2 * q], xv); fma2(a1, w[2 * q + 1], yv); }
                }
                float2 f0 = unpack2(a0), f1 = unpack2(a1), f2 = unpack2(a2), f3 = unpack2(a3);
                float dsum = ((f0.x + f0.y) + (f1.x + f1.y)) + ((f2.x + f2.y) + (f3.x + f3.y));
                dsum += __shfl_xor_sync(mask, dsum, 1);          // combine k-halves
                float av = 0.f;
                if (cc == 0) {
                    float gs = dsum + gxv;
                    av = (g == 2) ? ftanh(gs) : fsigmoid(gs);    // gate activation (even lanes)
                }
                float fv = __shfl_down_sync(mask, av, 2);
                float gv = __shfl_down_sync(mask, av, 4);
                float ov = __shfl_down_sync(mask, av, 6);
                if (sub == 0) {
                    cst = fv * cst + av * gv;
                    float h = ov * ftanh(cst);
                    const uint32_t off = (uint32_t)(bw * HID + base + u) * 4u;
#pragma unroll
                    for (int p = 0; p < CLSZ; p++) dsmem_st_f32(r_h[p] + off, h);
                }
            }
            gxv = gxn;
            cluster_sync_();       // release h_{t+1} writes; acquire for next step's reads
        }
        return;
    }

    // ---------------- consumer CTA ----------------
    unsigned long long wk[50];       // keys threads: WkT slice in registers
    if (tid >= 128 && tid < 208) {
        const int k = (tid - 128) >> 1, half = (tid - 128) & 1;
        const unsigned long long* wp =
            reinterpret_cast<const unsigned long long*>(g_WkT + k * HID + half * 100);
#pragma unroll
        for (int q = 0; q < 50; q++) wk[q] = wp[q];
    }
    unsigned long long M2[20];
    float wr = 0.f;
    for (int i = tid; i < HID; i += 256) S.Ws[i] = W_s[i];
    if (tid < KDIM) S.bk[tid] = b_k[tid];
    if (tid == 0)   S.bs = b_s[0];
    if (tid < NSLOT) {
#pragma unroll
        for (int q = 0; q < 20; q++) M2[q] = pack2(1e-6f, 1e-6f);
        wr = (tid == 0) ? 1.f : 0.f;
    }

    __syncthreads();
    cluster_sync_();   // h zeroed everywhere before any traffic

    for (int t = 0; t < TSTEPS; t++) {
        // keys(t-1) on warps 4-7 || MANN(t-2) on warps 0-3
        if (tid >= 128) {
            if (t >= 1) keys_sigma(S, tid, &S.h[t & 1][0], t & 1, wk);
        } else if (t >= 2) {
            mann_step(S, tid, (t - 1) & 1, M2, wr);
        }
        // cluster_sync doubles as the CTA-wide barrier (release/acquire, all threads)
        cluster_sync_();
    }

    // tail 1: keys for hiddens[4095] (in h[0]) || MANN for hiddens[4094] (key[1])
    if (tid >= 128) keys_sigma(S, tid, &S.h[0][0], 0, wk);
    else            mann_step(S, tid, 1, M2, wr);
    __syncthreads();
    // tail 2: MANN for hiddens[4095] (key[0])
    if (tid < 128)  mann_step(S, tid, 0, M2, wr);

    if (tid < NSLOT) {
#pragma unroll
        for (int q = 0; q < 20; q++) {
            float2 v = unpack2(M2[q]);
            out[tid * KDIM + 2 * q]     = v.x;
            out[tid * KDIM + 2 * q + 1] = v.y;
        }
    }
}

// ---------------- launch ----------------
extern "C" void kernel_launch(void* const* d_in, const int* in_sizes, int n_in,
                              void* d_out, int out_size) {
    const float* x    = (const float*)d_in[0];
    const float* y    = (const float*)d_in[1];
    const float* W_in = (const float*)d_in[2];
    const float* b_in = (const float*)d_in[3];
    const float* W_ih = (const float*)d_in[4];
    const float* W_hh = (const float*)d_in[5];
    const float* b_ih = (const float*)d_in[6];
    const float* b_hh = (const float*)d_in[7];
    const float* W_k  = (const float*)d_in[8];
    const float* b_k  = (const float*)d_in[9];
    const float* W_s  = (const float*)d_in[10];
    const float* b_s  = (const float*)d_in[11];
    // gamma (d_in[12]) provably unused: wlu mask is identically 1, wu/gamma cancel

    prep_kernel<<<(G4 * FDIM + 255) / 256, 256>>>(W_in, W_ih, b_ih, b_hh, W_k);
    fused_kernel<<<CLSZ + NWORK, 256>>>(W_hh, b_k, W_s, b_s, x, b_in, y, (float*)d_out);
}

// round 14
// speedup vs baseline: 1.1375x; 1.0298x over previous
#include <cuda_runtime.h>
#include <cstdint>
#include <math.h>

#define TSTEPS 4096
#define DIN    512
#define FDIM   256
#define HID    200
#define G4     800
#define KDIM   40
#define NSLOT  128
#define EPSF   1e-12f
#define CLSZ   8

// ---------------- scratch (device globals) ----------------
__device__ float g_xs[TSTEPS * FDIM];
__device__ float g_gx[TSTEPS * G4];
__device__ float g_WinT[FDIM * DIN];
__device__ float g_Wx[G4 * FDIM];
__device__ float g_wy[G4];
__device__ float g_bsum[G4];
__device__ float g_WkT[KDIM * HID];   // W_k transposed: [40][200]

// ---------------- helpers ----------------
__device__ __forceinline__ float fsigmoid(float x) {
    return __fdividef(1.f, 1.f + __expf(-x));
}
__device__ __forceinline__ float ftanh(float x) {
    float a = fabsf(x);
    float e = __expf(-2.f * a);
    float r = __fdividef(1.f - e, 1.f + e);
    return copysignf(r, x);
}
__device__ __forceinline__ uint32_t smem_u32(const void* p) {
    return (uint32_t)__cvta_generic_to_shared(p);
}
__device__ __forceinline__ uint32_t my_cluster_rank() {
    uint32_t r; asm("mov.u32 %0, %%cluster_ctarank;" : "=r"(r)); return r;
}
__device__ __forceinline__ uint32_t mapa_u32(uint32_t laddr, uint32_t rank) {
    uint32_t r;
    asm("mapa.shared::cluster.u32 %0, %1, %2;" : "=r"(r) : "r"(laddr), "r"(rank));
    return r;
}
__device__ __forceinline__ void cluster_sync_() {
    asm volatile("barrier.cluster.arrive.aligned;" ::: "memory");
    asm volatile("barrier.cluster.wait.aligned;" ::: "memory");
}
__device__ __forceinline__ void dsmem_st_f32(uint32_t raddr, float v) {
    asm volatile("st.shared::cluster.f32 [%0], %1;" :: "r"(raddr), "f"(v) : "memory");
}
// 16B vector load from shared (LDS.128) into two u64
__device__ __forceinline__ void lds128(unsigned long long& x, unsigned long long& y, uint32_t addr) {
    asm volatile("ld.shared.v2.u64 {%0, %1}, [%2];" : "=l"(x), "=l"(y) : "r"(addr));
}
// packed fp32x2 FMA: d = a*b + d  (sm_100 FFMA2; ptxas never auto-fuses this)
__device__ __forceinline__ void fma2(unsigned long long& d, unsigned long long a, unsigned long long b) {
    asm("fma.rn.f32x2 %0, %1, %2, %0;" : "+l"(d) : "l"(a), "l"(b));
}
__device__ __forceinline__ float2 unpack2(unsigned long long v) {
    float2 r; asm("mov.b64 {%0, %1}, %2;" : "=f"(r.x), "=f"(r.y) : "l"(v)); return r;
}
__device__ __forceinline__ unsigned long long pack2(float x, float y) {
    unsigned long long v; asm("mov.b64 %0, {%1, %2};" : "=l"(v) : "f"(x), "f"(y)); return v;
}

// ---------------- prep ----------------
__global__ void prep_kernel(const float* __restrict__ W_in, const float* __restrict__ W_ih,
                            const float* __restrict__ b_ih, const float* __restrict__ b_hh,
                            const float* __restrict__ W_k) {
    int idx = blockIdx.x * blockDim.x + threadIdx.x;
    if (idx < G4 * FDIM) {
        int n = idx / FDIM, k = idx % FDIM;
        g_Wx[idx] = W_ih[n * (FDIM + 1) + k];
    }
    if (idx < DIN * FDIM) {
        int k = idx / FDIM, n = idx % FDIM;
        g_WinT[n * DIN + k] = W_in[idx];
    }
    if (idx < G4) {
        g_wy[idx]   = W_ih[idx * (FDIM + 1) + FDIM];
        g_bsum[idx] = b_ih[idx] + b_hh[idx];
    }
    if (idx < KDIM * HID) {
        int k = idx / HID, h = idx % HID;
        g_WkT[idx] = W_k[h * KDIM + k];
    }
}

// ---------------- GEMM C = A * B^T ----------------
__device__ __forceinline__ void gemm_nt_body(
    const float* __restrict__ A, const float* __restrict__ B, float* __restrict__ C,
    int M, int N, int K,
    const float* __restrict__ bias, const float* __restrict__ yvec, const float* __restrict__ wy)
{
    __shared__ __align__(16) float As[16][64];
    __shared__ __align__(16) float Bs[16][64];
    const int m0 = blockIdx.y * 64, n0 = blockIdx.x * 64;
    const int tid = threadIdx.x;
    const int tx = tid % 16, ty = tid / 16;
    const int lr = tid / 4, lc4 = (tid % 4) * 4;

    float acc[4][4];
#pragma unroll
    for (int i = 0; i < 4; i++)
#pragma unroll
        for (int j = 0; j < 4; j++) acc[i][j] = 0.f;

    for (int k0 = 0; k0 < K; k0 += 16) {
        float4 av = *reinterpret_cast<const float4*>(A + (size_t)(m0 + lr) * K + k0 + lc4);
        As[lc4 + 0][lr] = av.x; As[lc4 + 1][lr] = av.y;
        As[lc4 + 2][lr] = av.z; As[lc4 + 3][lr] = av.w;
        float4 bv = make_float4(0.f, 0.f, 0.f, 0.f);
        if (n0 + lr < N) bv = *reinterpret_cast<const float4*>(B + (size_t)(n0 + lr) * K + k0 + lc4);
        Bs[lc4 + 0][lr] = bv.x; Bs[lc4 + 1][lr] = bv.y;
        Bs[lc4 + 2][lr] = bv.z; Bs[lc4 + 3][lr] = bv.w;
        __syncthreads();
#pragma unroll
        for (int kk = 0; kk < 16; kk++) {
            float4 a4 = *reinterpret_cast<const float4*>(&As[kk][ty * 4]);
            float4 b4 = *reinterpret_cast<const float4*>(&Bs[kk][tx * 4]);
            float aa[4] = {a4.x, a4.y, a4.z, a4.w};
            float bb[4] = {b4.x, b4.y, b4.z, b4.w};
#pragma unroll
            for (int i = 0; i < 4; i++)
#pragma unroll
                for (int j = 0; j < 4; j++) acc[i][j] = fmaf(aa[i], bb[j], acc[i][j]);
        }
        __syncthreads();
    }
#pragma unroll
    for (int i = 0; i < 4; i++) {
        int m = m0 + ty * 4 + i;
        float yv = 0.f;
        if (yvec) yv = (m == 0) ? 0.f : yvec[m - 1];
#pragma unroll
        for (int j = 0; j < 4; j++) {
            int n = n0 + tx * 4 + j;
            if (n < N) {
                float v = acc[i][j] + (bias ? bias[n] : 0.f);
                if (wy) v = fmaf(yv, wy[n], v);
                C[(size_t)m * N + n] = v;
            }
        }
    }
}

__global__ void __launch_bounds__(256) gemm1_kernel(const float* __restrict__ x,
                                                    const float* __restrict__ b_in) {
    gemm_nt_body(x, g_WinT, g_xs, TSTEPS, FDIM, DIN, b_in, nullptr, nullptr);
}
__global__ void __launch_bounds__(256) gemm2_kernel(const float* __restrict__ y) {
    gemm_nt_body(g_xs, g_Wx, g_gx, TSTEPS, G4, FDIM, g_bsum, y, g_wy);
}

// ---------------- fused kernel shared state ----------------
struct Shm {
    __align__(16) float h[2][HID];          // double-buffered hidden (dsmem broadcast target)
    __align__(8)  float Ws[HID];
    __align__(8)  float bk[KDIM];
    __align__(16) float key[2][KDIM];       // double-buffered (keys pipeline vs MANN)
    __align__(16) float kn[2][KDIM];
    float sig[2];
    float wsum[2][4];                       // double-buffered warp partials (deferred softmax)
    float bs;
};

// MANN step on key buffer kb, writing warp partials to wsum[wb] (threads 0..127).
// Softmax normalization DEFERRED: wr for this step is finalized here from last
// step's partials (wsum[wb^1]) + carried e_prev — no bar.sync, no tail divide.
// Cross-step wsum ordering is provided by the caller's cluster_sync/__syncthreads.
__device__ __forceinline__ void mann_step(Shm& S, int tid, int kb, int wb, bool first,
                                          unsigned long long* M2, float& e_prev)
{
    float wr;
    if (first) {
        wr = (tid == 0) ? 1.f : 0.f;
    } else {
        float tot = (S.wsum[wb ^ 1][0] + S.wsum[wb ^ 1][1])
                  + (S.wsum[wb ^ 1][2] + S.wsum[wb ^ 1][3]);
        wr = __fdividef(e_prev, tot);
    }
    const float sg = S.sig[kb];
    const float ww = fmaf(sg, wr, 1.f - sg);        // wlu mask == 1 identically
    const unsigned long long ww2 = pack2(ww, ww);
    const uint32_t kaddr  = smem_u32(&S.key[kb][0]);
    const uint32_t knaddr = smem_u32(&S.kn[kb][0]);
    unsigned long long n0 = 0, n1 = 0, d0 = 0, d1 = 0;
#pragma unroll
    for (int q = 0; q < 20; q += 2) {
        unsigned long long k0, k1, kn0, kn1;
        lds128(k0,  k1,  kaddr  + (uint32_t)q * 8u);
        lds128(kn0, kn1, knaddr + (uint32_t)q * 8u);
        fma2(M2[q],     ww2, k0);
        fma2(M2[q + 1], ww2, k1);
        fma2(n0, M2[q],     M2[q]);
        fma2(n1, M2[q + 1], M2[q + 1]);
        fma2(d0, M2[q],     kn0);
        fma2(d1, M2[q + 1], kn1);
    }
    float2 na = unpack2(n0), nb = unpack2(n1), da = unpack2(d0), db = unpack2(d1);
    float ns  = (na.x + na.y) + (nb.x + nb.y);      // >= 4e-11, never 0
    float dot = (da.x + da.y) + (db.x + db.y);
    float e = __expf(dot * rsqrtf(ns));             // |logit| <= sqrt(40)
    float acc = e;
#pragma unroll
    for (int off = 16; off > 0; off >>= 1) acc += __shfl_xor_sync(0xffffffffu, acc, off);
    if ((tid & 31) == 0) S.wsum[wb][tid >> 5] = acc;
    e_prev = e;                                     // normalized next step
}

// keys + sigma from hidden vector hb into buffer kb (threads 128..215)
__device__ __forceinline__ void keys_sigma(Shm& S, int tid, const float* __restrict__ hb, int kb,
                                           const unsigned long long* wk)
{
    if (tid < 208) {                 // keys: 2 threads per output (tid 128..207)
        const int k = (tid - 128) >> 1, half = (tid - 128) & 1;
        const unsigned mask = (tid < 192) ? 0xffffffffu : 0x0000FFFFu;
        const uint32_t haddr = smem_u32(hb) + (uint32_t)half * 400u;
        unsigned long long a0 = 0, a1 = 0, a2 = 0, a3 = 0;
#pragma unroll
        for (int q = 0; q < 25; q++) {
            unsigned long long x, y;
            lds128(x, y, haddr + (uint32_t)q * 16u);
            if (q & 1) { fma2(a2, wk[2 * q], x); fma2(a3, wk[2 * q + 1], y); }
            else       { fma2(a0, wk[2 * q], x); fma2(a1, wk[2 * q + 1], y); }
        }
        float2 xa = unpack2(a0), xb = unpack2(a1), xc = unpack2(a2), xd = unpack2(a3);
        float acc = ((xa.x + xa.y) + (xb.x + xb.y)) + ((xc.x + xc.y) + (xd.x + xd.y));
        acc += __shfl_xor_sync(mask, acc, 1);
        if (half == 0) {
            float kv = ftanh(acc + S.bk[k]);
            S.key[kb][k] = kv;
            S.kn[kb][k]  = kv / fmaxf(fabsf(kv), EPSF);
        }
    } else if (tid < 216) {          // sigma: 8 threads (warp 6 lanes 16..23)
        const int p = tid - 208;
        float a = 0.f;
#pragma unroll
        for (int i = 0; i < 25; i++) a = fmaf(hb[p * 25 + i], S.Ws[p * 25 + i], a);
        a += __shfl_xor_sync(0x00FF0000u, a, 4);
        a += __shfl_xor_sync(0x00FF0000u, a, 2);
        a += __shfl_xor_sync(0x00FF0000u, a, 1);
        if (p == 0) S.sig[kb] = fsigmoid(a + S.bs);
    }
}

__global__ void __cluster_dims__(CLSZ, 1, 1) __launch_bounds__(256, 1)
fused_kernel(const float* __restrict__ W_hh,
             const float* __restrict__ b_k,
             const float* __restrict__ W_s, const float* __restrict__ b_s,
             float* __restrict__ out)
{
    __shared__ Shm S;
    const int tid = threadIdx.x;
    const uint32_t rank = my_cluster_rank();
    const bool is_consumer = (rank == CLSZ - 1);

    if (tid < HID) { S.h[0][tid] = 0.f; S.h[1][tid] = 0.f; }

    if (!is_consumer) {
        // ================= LSTM producer (R11-identical) =================
        const int units = (rank < 6) ? 29 : 26;
        const int base  = 29 * (int)rank;            // rank 6 -> 174
        const int nact  = 8 * units;
        const bool act  = tid < nact;
        const int u   = tid >> 3;                    // unit within CTA
        const int sub = tid & 7;                     // 2*gate + cc
        const int g   = sub >> 1;
        const int cc  = sub & 1;
        const int grow = act ? (g * HID + base + u) : 0;

        unsigned long long w[50];
        if (act) {
            const unsigned long long* wp =
                reinterpret_cast<const unsigned long long*>(W_hh + (size_t)grow * HID + cc * 100);
#pragma unroll
            for (int q = 0; q < 50; q++) w[q] = wp[q];
        }
        unsigned mask = 0;
        if (act) {
            int rem = nact - (tid & ~31);
            mask = (rem >= 32) ? 0xffffffffu : ((1u << rem) - 1u);
        }
        uint32_t r_h[CLSZ];
        if (act && sub == 0) {
            uint32_t hA = smem_u32(&S.h[0][0]);
#pragma unroll
            for (int p = 0; p < CLSZ; p++) r_h[p] = mapa_u32(hA, (uint32_t)p);
        }

        __syncthreads();
        cluster_sync_();   // h zeroed everywhere before any traffic

        float cst = 0.f;
        float gxv = (act && cc == 0) ? g_gx[grow] : 0.f;

        for (int t = 0; t < TSTEPS; t++) {
            const int buf = t & 1, bw = buf ^ 1;
            float gxn = 0.f;
            if (act && cc == 0) {
                int tn = (t + 1 < TSTEPS) ? (t + 1) : t;   // prefetch next gx
                gxn = g_gx[(size_t)tn * G4 + grow];
            }
            if (act) {
                const uint32_t haddr = smem_u32(&S.h[buf][0]) + (uint32_t)cc * 400u;
                unsigned long long a0 = 0, a1 = 0, a2 = 0, a3 = 0;
#pragma unroll
                for (int q = 0; q < 25; q++) {
                    unsigned long long x, y;
                    lds128(x, y, haddr + (uint32_t)q * 16u);
                    if (q & 1) { fma2(a2, w[2 * q], x); fma2(a3, w[2 * q + 1], y); }
                    else       { fma2(a0, w[2 * q], x); fma2(a1, w[2 * q + 1], y); }
                }
                float2 f0 = unpack2(a0), f1 = unpack2(a1), f2 = unpack2(a2), f3 = unpack2(a3);
                float dsum = ((f0.x + f0.y) + (f1.x + f1.y)) + ((f2.x + f2.y) + (f3.x + f3.y));
                dsum += __shfl_xor_sync(mask, dsum, 1);          // combine k-halves
                float av = 0.f;
                if (cc == 0) {
                    float gs = dsum + gxv;
                    av = (g == 2) ? ftanh(gs) : fsigmoid(gs);    // gate activation (even lanes)
                }
                float fv = __shfl_down_sync(mask, av, 2);
                float gv = __shfl_down_sync(mask, av, 4);
                float ov = __shfl_down_sync(mask, av, 6);
                if (sub == 0) {
                    cst = fv * cst + av * gv;
                    float h = ov * ftanh(cst);
                    const uint32_t off = (uint32_t)(bw * HID + base + u) * 4u;
#pragma unroll
                    for (int p = 0; p < CLSZ; p++) dsmem_st_f32(r_h[p] + off, h);
                }
            }
            gxv = gxn;
            cluster_sync_();       // release h_{t+1} writes; acquire for next step's reads
        }
        return;
    }

    // ================= consumer CTA =================
    unsigned long long wk[50];       // keys threads: WkT slice in registers
    if (tid >= 128 && tid < 208) {
        const int k = (tid - 128) >> 1, half = (tid - 128) & 1;
        const unsigned long long* wp =
            reinterpret_cast<const unsigned long long*>(g_WkT + k * HID + half * 100);
#pragma unroll
        for (int q = 0; q < 50; q++) wk[q] = wp[q];
    }
    unsigned long long M2[20];
    float e_prev = 0.f;
    for (int i = tid; i < HID; i += 256) S.Ws[i] = W_s[i];
    if (tid < KDIM) S.bk[tid] = b_k[tid];
    if (tid == 0)   S.bs = b_s[0];
    if (tid < NSLOT) {
#pragma unroll
        for (int q = 0; q < 20; q++) M2[q] = pack2(1e-6f, 1e-6f);
    }

    __syncthreads();
    cluster_sync_();   // h zeroed everywhere before any traffic

    for (int t = 0; t < TSTEPS; t++) {
        // keys(t-1) on warps 4-7 || MANN invocation i=t-2 on warps 0-3
        if (tid >= 128) {
            if (t >= 1) keys_sigma(S, tid, &S.h[t & 1][0], t & 1, wk);
        } else if (t >= 2) {
            const int i = t - 2;
            mann_step(S, tid, (t - 1) & 1, i & 1, i == 0, M2, e_prev);
        }
        // cluster_sync doubles as the CTA-wide barrier (orders wsum across steps too)
        cluster_sync_();
    }

    // tail 1: keys for hiddens[4095] (in h[0]) || MANN i=4094 (key[1], wsum wb=0)
    if (tid >= 128) keys_sigma(S, tid, &S.h[0][0], 0, wk);
    else            mann_step(S, tid, 1, 0, false, M2, e_prev);
    __syncthreads();
    // tail 2: MANN i=4095 (key[0], wsum wb=1)
    if (tid < 128)  mann_step(S, tid, 0, 1, false, M2, e_prev);

    if (tid < NSLOT) {
#pragma unroll
        for (int q = 0; q < 20; q++) {
            float2 v = unpack2(M2[q]);
            out[tid * KDIM + 2 * q]     = v.x;
            out[tid * KDIM + 2 * q + 1] = v.y;
        }
    }
}

// ---------------- launch ----------------
extern "C" void kernel_launch(void* const* d_in, const int* in_sizes, int n_in,
                              void* d_out, int out_size) {
    const float* x    = (const float*)d_in[0];
    const float* y    = (const float*)d_in[1];
    const float* W_in = (const float*)d_in[2];
    const float* b_in = (const float*)d_in[3];
    const float* W_ih = (const float*)d_in[4];
    const float* W_hh = (const float*)d_in[5];
    const float* b_ih = (const float*)d_in[6];
    const float* b_hh = (const float*)d_in[7];
    const float* W_k  = (const float*)d_in[8];
    const float* b_k  = (const float*)d_in[9];
    const float* W_s  = (const float*)d_in[10];
    const float* b_s  = (const float*)d_in[11];
    // gamma (d_in[12]) provably unused: wlu mask is identically 1, wu/gamma cancel

    prep_kernel<<<(G4 * FDIM + 255) / 256, 256>>>(W_in, W_ih, b_ih, b_hh, W_k);
    gemm1_kernel<<<dim3(FDIM / 64, TSTEPS / 64), 256>>>(x, b_in);
    gemm2_kernel<<<dim3((G4 + 63) / 64, TSTEPS / 64), 256>>>(y);
    fused_kernel<<<CLSZ, 256>>>(W_hh, b_k, W_s, b_s, (float*)d_out);
}

// round 15
// speedup vs baseline: 1.2727x; 1.1188x over previous
#include <cuda_runtime.h>
#include <cstdint>
#include <math.h>

#define TSTEPS 4096
#define DIN    512
#define FDIM   256
#define HID    200
#define G4     800
#define KDIM   40
#define NSLOT  128
#define EPSF   1e-12f
#define CLSZ   8

// ---------------- scratch (device globals) ----------------
__device__ float g_xs[TSTEPS * FDIM];
__device__ float g_gx[TSTEPS * G4];
__device__ float g_WinT[FDIM * DIN];
__device__ float g_Wx[G4 * FDIM];
__device__ float g_wy[G4];
__device__ float g_bsum[G4];
__device__ float g_WkT[KDIM * HID];   // W_k transposed: [40][200]

// ---------------- helpers ----------------
__device__ __forceinline__ float fsigmoid(float x) {
    return __fdividef(1.f, 1.f + __expf(-x));
}
__device__ __forceinline__ float ftanh(float x) {
    float a = fabsf(x);
    float e = __expf(-2.f * a);
    float r = __fdividef(1.f - e, 1.f + e);
    return copysignf(r, x);
}
// hardware tanh (MUFU.TANH, sm_75+): 1 op, ~16cyc, max err ~2^-11 — producer only
__device__ __forceinline__ float tanh_ap(float x) {
    float r; asm("tanh.approx.f32 %0, %1;" : "=f"(r) : "f"(x)); return r;
}
__device__ __forceinline__ float sig_ap(float x) {
    return fmaf(tanh_ap(0.5f * x), 0.5f, 0.5f);
}
__device__ __forceinline__ uint32_t smem_u32(const void* p) {
    return (uint32_t)__cvta_generic_to_shared(p);
}
__device__ __forceinline__ uint32_t my_cluster_rank() {
    uint32_t r; asm("mov.u32 %0, %%cluster_ctarank;" : "=r"(r)); return r;
}
__device__ __forceinline__ uint32_t mapa_u32(uint32_t laddr, uint32_t rank) {
    uint32_t r;
    asm("mapa.shared::cluster.u32 %0, %1, %2;" : "=r"(r) : "r"(laddr), "r"(rank));
    return r;
}
__device__ __forceinline__ void cluster_sync_() {
    asm volatile("barrier.cluster.arrive.aligned;" ::: "memory");
    asm volatile("barrier.cluster.wait.aligned;" ::: "memory");
}
__device__ __forceinline__ void dsmem_st_f32(uint32_t raddr, float v) {
    asm volatile("st.shared::cluster.f32 [%0], %1;" :: "r"(raddr), "f"(v) : "memory");
}
__device__ __forceinline__ void bar_sync_(int id, int cnt) {
    asm volatile("bar.sync %0, %1;" :: "r"(id), "r"(cnt) : "memory");
}
// 16B vector load from shared (LDS.128) into two u64
__device__ __forceinline__ void lds128(unsigned long long& x, unsigned long long& y, uint32_t addr) {
    asm volatile("ld.shared.v2.u64 {%0, %1}, [%2];" : "=l"(x), "=l"(y) : "r"(addr));
}
// packed fp32x2 FMA: d = a*b + d  (sm_100 FFMA2; ptxas never auto-fuses this)
__device__ __forceinline__ void fma2(unsigned long long& d, unsigned long long a, unsigned long long b) {
    asm("fma.rn.f32x2 %0, %1, %2, %0;" : "+l"(d) : "l"(a), "l"(b));
}
__device__ __forceinline__ float2 unpack2(unsigned long long v) {
    float2 r; asm("mov.b64 {%0, %1}, %2;" : "=f"(r.x), "=f"(r.y) : "l"(v)); return r;
}
__device__ __forceinline__ unsigned long long pack2(float x, float y) {
    unsigned long long v; asm("mov.b64 %0, {%1, %2};" : "=l"(v) : "f"(x), "f"(y)); return v;
}

// ---------------- prep ----------------
__global__ void prep_kernel(const float* __restrict__ W_in, const float* __restrict__ W_ih,
                            const float* __restrict__ b_ih, const float* __restrict__ b_hh,
                            const float* __restrict__ W_k) {
    int idx = blockIdx.x * blockDim.x + threadIdx.x;
    if (idx < G4 * FDIM) {
        int n = idx / FDIM, k = idx % FDIM;
        g_Wx[idx] = W_ih[n * (FDIM + 1) + k];
    }
    if (idx < DIN * FDIM) {
        int k = idx / FDIM, n = idx % FDIM;
        g_WinT[n * DIN + k] = W_in[idx];
    }
    if (idx < G4) {
        g_wy[idx]   = W_ih[idx * (FDIM + 1) + FDIM];
        g_bsum[idx] = b_ih[idx] + b_hh[idx];
    }
    if (idx < KDIM * HID) {
        int k = idx / HID, h = idx % HID;
        g_WkT[idx] = W_k[h * KDIM + k];
    }
}

// ---------------- GEMM C = A * B^T ----------------
__device__ __forceinline__ void gemm_nt_body(
    const float* __restrict__ A, const float* __restrict__ B, float* __restrict__ C,
    int M, int N, int K,
    const float* __restrict__ bias, const float* __restrict__ yvec, const float* __restrict__ wy)
{
    __shared__ __align__(16) float As[16][64];
    __shared__ __align__(16) float Bs[16][64];
    const int m0 = blockIdx.y * 64, n0 = blockIdx.x * 64;
    const int tid = threadIdx.x;
    const int tx = tid % 16, ty = tid / 16;
    const int lr = tid / 4, lc4 = (tid % 4) * 4;

    float acc[4][4];
#pragma unroll
    for (int i = 0; i < 4; i++)
#pragma unroll
        for (int j = 0; j < 4; j++) acc[i][j] = 0.f;

    for (int k0 = 0; k0 < K; k0 += 16) {
        float4 av = *reinterpret_cast<const float4*>(A + (size_t)(m0 + lr) * K + k0 + lc4);
        As[lc4 + 0][lr] = av.x; As[lc4 + 1][lr] = av.y;
        As[lc4 + 2][lr] = av.z; As[lc4 + 3][lr] = av.w;
        float4 bv = make_float4(0.f, 0.f, 0.f, 0.f);
        if (n0 + lr < N) bv = *reinterpret_cast<const float4*>(B + (size_t)(n0 + lr) * K + k0 + lc4);
        Bs[lc4 + 0][lr] = bv.x; Bs[lc4 + 1][lr] = bv.y;
        Bs[lc4 + 2][lr] = bv.z; Bs[lc4 + 3][lr] = bv.w;
        __syncthreads();
#pragma unroll
        for (int kk = 0; kk < 16; kk++) {
            float4 a4 = *reinterpret_cast<const float4*>(&As[kk][ty * 4]);
            float4 b4 = *reinterpret_cast<const float4*>(&Bs[kk][tx * 4]);
            float aa[4] = {a4.x, a4.y, a4.z, a4.w};
            float bb[4] = {b4.x, b4.y, b4.z, b4.w};
#pragma unroll
            for (int i = 0; i < 4; i++)
#pragma unroll
                for (int j = 0; j < 4; j++) acc[i][j] = fmaf(aa[i], bb[j], acc[i][j]);
        }
        __syncthreads();
    }
#pragma unroll
    for (int i = 0; i < 4; i++) {
        int m = m0 + ty * 4 + i;
        float yv = 0.f;
        if (yvec) yv = (m == 0) ? 0.f : yvec[m - 1];
#pragma unroll
        for (int j = 0; j < 4; j++) {
            int n = n0 + tx * 4 + j;
            if (n < N) {
                float v = acc[i][j] + (bias ? bias[n] : 0.f);
                if (wy) v = fmaf(yv, wy[n], v);
                C[(size_t)m * N + n] = v;
            }
        }
    }
}

__global__ void __launch_bounds__(256) gemm1_kernel(const float* __restrict__ x,
                                                    const float* __restrict__ b_in) {
    gemm_nt_body(x, g_WinT, g_xs, TSTEPS, FDIM, DIN, b_in, nullptr, nullptr);
}
__global__ void __launch_bounds__(256) gemm2_kernel(const float* __restrict__ y) {
    gemm_nt_body(g_xs, g_Wx, g_gx, TSTEPS, G4, FDIM, g_bsum, y, g_wy);
}

// ---------------- fused kernel shared state ----------------
struct Shm {
    __align__(16) float h[2][HID];          // double-buffered hidden (dsmem broadcast target)
    __align__(8)  float Ws[HID];
    __align__(8)  float bk[KDIM];
    __align__(16) float key[2][KDIM];       // double-buffered (keys pipeline vs MANN)
    __align__(16) float kn[2][KDIM];
    float sig[2];
    float wsum[4];
    float bs;
};

// MANN step on buffer kb (threads 0..127 only; uses named barrier 1)
__device__ __forceinline__ void mann_step(Shm& S, int tid, int kb,
                                          unsigned long long* M2, float& wr)
{
    const float sg = S.sig[kb];
    const float ww = fmaf(sg, wr, 1.f - sg);        // wlu mask == 1 identically
    const unsigned long long ww2 = pack2(ww, ww);
    const uint32_t kaddr  = smem_u32(&S.key[kb][0]);
    const uint32_t knaddr = smem_u32(&S.kn[kb][0]);
    unsigned long long n0 = 0, n1 = 0, d0 = 0, d1 = 0;
#pragma unroll
    for (int q = 0; q < 20; q += 2) {
        unsigned long long k0, k1, kn0, kn1;
        lds128(k0,  k1,  kaddr  + (uint32_t)q * 8u);
        lds128(kn0, kn1, knaddr + (uint32_t)q * 8u);
        fma2(M2[q],     ww2, k0);
        fma2(M2[q + 1], ww2, k1);
        fma2(n0, M2[q],     M2[q]);
        fma2(n1, M2[q + 1], M2[q + 1]);
        fma2(d0, M2[q],     kn0);
        fma2(d1, M2[q + 1], kn1);
    }
    float2 na = unpack2(n0), nb = unpack2(n1), da = unpack2(d0), db = unpack2(d1);
    float ns  = (na.x + na.y) + (nb.x + nb.y);      // >= 4e-11, never 0
    float dot = (da.x + da.y) + (db.x + db.y);
    float e = __expf(dot * rsqrtf(ns));             // |logit| <= sqrt(40)
    float acc = e;
#pragma unroll
    for (int off = 16; off > 0; off >>= 1) acc += __shfl_xor_sync(0xffffffffu, acc, off);
    if ((tid & 31) == 0) S.wsum[tid >> 5] = acc;
    bar_sync_(1, 128);                              // MANN group only
    float tot = (S.wsum[0] + S.wsum[1]) + (S.wsum[2] + S.wsum[3]);
    wr = __fdividef(e, tot);
}

// keys + sigma from hidden vector hb into buffer kb (threads 128..215)
__device__ __forceinline__ void keys_sigma(Shm& S, int tid, const float* __restrict__ hb, int kb,
                                           const unsigned long long* wk)
{
    if (tid < 208) {                 // keys: 2 threads per output (tid 128..207)
        const int k = (tid - 128) >> 1, half = (tid - 128) & 1;
        const unsigned mask = (tid < 192) ? 0xffffffffu : 0x0000FFFFu;
        const uint32_t haddr = smem_u32(hb) + (uint32_t)half * 400u;
        unsigned long long a0 = 0, a1 = 0, a2 = 0, a3 = 0;
#pragma unroll
        for (int q = 0; q < 25; q++) {
            unsigned long long x, y;
            lds128(x, y, haddr + (uint32_t)q * 16u);
            if (q & 1) { fma2(a2, wk[2 * q], x); fma2(a3, wk[2 * q + 1], y); }
            else       { fma2(a0, wk[2 * q], x); fma2(a1, wk[2 * q + 1], y); }
        }
        float2 xa = unpack2(a0), xb = unpack2(a1), xc = unpack2(a2), xd = unpack2(a3);
        float acc = ((xa.x + xa.y) + (xb.x + xb.y)) + ((xc.x + xc.y) + (xd.x + xd.y));
        acc += __shfl_xor_sync(mask, acc, 1);
        if (half == 0) {
            float kv = ftanh(acc + S.bk[k]);        // precise path (feeds output M)
            S.key[kb][k] = kv;
            S.kn[kb][k]  = kv / fmaxf(fabsf(kv), EPSF);
        }
    } else if (tid < 216) {          // sigma: 8 threads (warp 6 lanes 16..23)
        const int p = tid - 208;
        float a = 0.f;
#pragma unroll
        for (int i = 0; i < 25; i++) a = fmaf(hb[p * 25 + i], S.Ws[p * 25 + i], a);
        a += __shfl_xor_sync(0x00FF0000u, a, 4);
        a += __shfl_xor_sync(0x00FF0000u, a, 2);
        a += __shfl_xor_sync(0x00FF0000u, a, 1);
        if (p == 0) S.sig[kb] = fsigmoid(a + S.bs);
    }
}

__global__ void __cluster_dims__(CLSZ, 1, 1) __launch_bounds__(256, 1)
fused_kernel(const float* __restrict__ W_hh,
             const float* __restrict__ b_k,
             const float* __restrict__ W_s, const float* __restrict__ b_s,
             float* __restrict__ out)
{
    __shared__ Shm S;
    const int tid = threadIdx.x;
    const uint32_t rank = my_cluster_rank();
    const bool is_consumer = (rank == CLSZ - 1);

    if (tid < HID) { S.h[0][tid] = 0.f; S.h[1][tid] = 0.f; }

    if (!is_consumer) {
        // ================= LSTM producer (R11 + tanh.approx gates) =================
        const int units = (rank < 6) ? 29 : 26;
        const int base  = 29 * (int)rank;            // rank 6 -> 174
        const int nact  = 8 * units;
        const bool act  = tid < nact;
        const int u   = tid >> 3;                    // unit within CTA
        const int sub = tid & 7;                     // 2*gate + cc
        const int g   = sub >> 1;
        const int cc  = sub & 1;
        const int grow = act ? (g * HID + base + u) : 0;

        unsigned long long w[50];
        if (act) {
            const unsigned long long* wp =
                reinterpret_cast<const unsigned long long*>(W_hh + (size_t)grow * HID + cc * 100);
#pragma unroll
            for (int q = 0; q < 50; q++) w[q] = wp[q];
        }
        unsigned mask = 0;
        if (act) {
            int rem = nact - (tid & ~31);
            mask = (rem >= 32) ? 0xffffffffu : ((1u << rem) - 1u);
        }
        uint32_t r_h[CLSZ];
        if (act && sub == 0) {
            uint32_t hA = smem_u32(&S.h[0][0]);
#pragma unroll
            for (int p = 0; p < CLSZ; p++) r_h[p] = mapa_u32(hA, (uint32_t)p);
        }

        __syncthreads();
        cluster_sync_();   // h zeroed everywhere before any traffic

        float cst = 0.f;
        float gxv = (act && cc == 0) ? g_gx[grow] : 0.f;

        for (int t = 0; t < TSTEPS; t++) {
            const int buf = t & 1, bw = buf ^ 1;
            float gxn = 0.f;
            if (act && cc == 0) {
                int tn = (t + 1 < TSTEPS) ? (t + 1) : t;   // prefetch next gx
                gxn = g_gx[(size_t)tn * G4 + grow];
            }
            if (act) {
                const uint32_t haddr = smem_u32(&S.h[buf][0]) + (uint32_t)cc * 400u;
                unsigned long long a0 = 0, a1 = 0, a2 = 0, a3 = 0;
#pragma unroll
                for (int q = 0; q < 25; q++) {
                    unsigned long long x, y;
                    lds128(x, y, haddr + (uint32_t)q * 16u);
                    if (q & 1) { fma2(a2, w[2 * q], x); fma2(a3, w[2 * q + 1], y); }
                    else       { fma2(a0, w[2 * q], x); fma2(a1, w[2 * q + 1], y); }
                }
                float2 f0 = unpack2(a0), f1 = unpack2(a1), f2 = unpack2(a2), f3 = unpack2(a3);
                float dsum = ((f0.x + f0.y) + (f1.x + f1.y)) + ((f2.x + f2.y) + (f3.x + f3.y));
                dsum += __shfl_xor_sync(mask, dsum, 1);          // combine k-halves
                float av = 0.f;
                if (cc == 0) {
                    float gs = dsum + gxv;
                    // MUFU.TANH fast path (err ~2^-11; LSTM gates tolerate it)
                    av = (g == 2) ? tanh_ap(gs) : sig_ap(gs);
                }
                float fv = __shfl_down_sync(mask, av, 2);
                float gv = __shfl_down_sync(mask, av, 4);
                float ov = __shfl_down_sync(mask, av, 6);
                if (sub == 0) {
                    cst = fv * cst + av * gv;
                    float h = ov * tanh_ap(cst);
                    const uint32_t off = (uint32_t)(bw * HID + base + u) * 4u;
#pragma unroll
                    for (int p = 0; p < CLSZ; p++) dsmem_st_f32(r_h[p] + off, h);
                }
            }
            gxv = gxn;
            cluster_sync_();       // release h_{t+1} writes; acquire for next step's reads
        }
        return;
    }

    // ================= consumer CTA (R11-identical) =================
    unsigned long long wk[50];       // keys threads: WkT slice in registers
    if (tid >= 128 && tid < 208) {
        const int k = (tid - 128) >> 1, half = (tid - 128) & 1;
        const unsigned long long* wp =
            reinterpret_cast<const unsigned long long*>(g_WkT + k * HID + half * 100);
#pragma unroll
        for (int q = 0; q < 50; q++) wk[q] = wp[q];
    }
    unsigned long long M2[20];
    float wr = 0.f;
    for (int i = tid; i < HID; i += 256) S.Ws[i] = W_s[i];
    if (tid < KDIM) S.bk[tid] = b_k[tid];
    if (tid == 0)   S.bs = b_s[0];
    if (tid < NSLOT) {
#pragma unroll
        for (int q = 0; q < 20; q++) M2[q] = pack2(1e-6f, 1e-6f);
        wr = (tid == 0) ? 1.f : 0.f;
    }

    __syncthreads();
    cluster_sync_();   // h zeroed everywhere before any traffic

    for (int t = 0; t < TSTEPS; t++) {
        // keys(t-1) on warps 4-7 || MANN(t-2) on warps 0-3
        if (tid >= 128) {
            if (t >= 1) keys_sigma(S, tid, &S.h[t & 1][0], t & 1, wk);
        } else if (t >= 2) {
            mann_step(S, tid, (t - 1) & 1, M2, wr);
        }
        // cluster_sync doubles as the CTA-wide barrier (release/acquire, all threads)
        cluster_sync_();
    }

    // tail 1: keys for hiddens[4095] (in h[0]) || MANN for hiddens[4094] (key[1])
    if (tid >= 128) keys_sigma(S, tid, &S.h[0][0], 0, wk);
    else            mann_step(S, tid, 1, M2, wr);
    __syncthreads();
    // tail 2: MANN for hiddens[4095] (key[0])
    if (tid < 128)  mann_step(S, tid, 0, M2, wr);

    if (tid < NSLOT) {
#pragma unroll
        for (int q = 0; q < 20; q++) {
            float2 v = unpack2(M2[q]);
            out[tid * KDIM + 2 * q]     = v.x;
            out[tid * KDIM + 2 * q + 1] = v.y;
        }
    }
}

// ---------------- launch ----------------
extern "C" void kernel_launch(void* const* d_in, const int* in_sizes, int n_in,
                              void* d_out, int out_size) {
    const float* x    = (const float*)d_in[0];
    const float* y    = (const float*)d_in[1];
    const float* W_in = (const float*)d_in[2];
    const float* b_in = (const float*)d_in[3];
    const float* W_ih = (const float*)d_in[4];
    const float* W_hh = (const float*)d_in[5];
    const float* b_ih = (const float*)d_in[6];
    const float* b_hh = (const float*)d_in[7];
    const float* W_k  = (const float*)d_in[8];
    const float* b_k  = (const float*)d_in[9];
    const float* W_s  = (const float*)d_in[10];
    const float* b_s  = (const float*)d_in[11];
    // gamma (d_in[12]) provably unused: wlu mask is identically 1, wu/gamma cancel

    prep_kernel<<<(G4 * FDIM + 255) / 256, 256>>>(W_in, W_ih, b_ih, b_hh, W_k);
    gemm1_kernel<<<dim3(FDIM / 64, TSTEPS / 64), 256>>>(x, b_in);
    gemm2_kernel<<<dim3((G4 + 63) / 64, TSTEPS / 64), 256>>>(y);
    fused_kernel<<<CLSZ, 256>>>(W_hh, b_k, W_s, b_s, (float*)d_out);
}

// round 16
// speedup vs baseline: 1.4470x; 1.1370x over previous
#include <cuda_runtime.h>
#include <cstdint>
#include <math.h>

#define TSTEPS 4096
#define DIN    512
#define FDIM   256
#define HID    200
#define G4     800
#define KDIM   40
#define NSLOT  128
#define EPSF   1e-12f
#define CLSZ   8
#define TXB    804u    // 800B h-data + 4B consumer dummy, every barrier every phase

// ---------------- scratch (device globals) ----------------
__device__ float g_xs[TSTEPS * FDIM];
__device__ float g_gx[TSTEPS * G4];
__device__ float g_WinT[FDIM * DIN];
__device__ float g_Wx[G4 * FDIM];
__device__ float g_wy[G4];
__device__ float g_bsum[G4];
__device__ float g_WkT[KDIM * HID];   // W_k transposed: [40][200]

// ---------------- helpers ----------------
__device__ __forceinline__ float fsigmoid(float x) {
    return __fdividef(1.f, 1.f + __expf(-x));
}
__device__ __forceinline__ float ftanh(float x) {
    float a = fabsf(x);
    float e = __expf(-2.f * a);
    float r = __fdividef(1.f - e, 1.f + e);
    return copysignf(r, x);
}
// hardware tanh (MUFU.TANH): 1 op, max err ~2^-11 — producer gates only
__device__ __forceinline__ float tanh_ap(float x) {
    float r; asm("tanh.approx.f32 %0, %1;" : "=f"(r) : "f"(x)); return r;
}
__device__ __forceinline__ float sig_ap(float x) {
    return fmaf(tanh_ap(0.5f * x), 0.5f, 0.5f);
}
__device__ __forceinline__ uint32_t smem_u32(const void* p) {
    return (uint32_t)__cvta_generic_to_shared(p);
}
__device__ __forceinline__ uint32_t my_cluster_rank() {
    uint32_t r; asm("mov.u32 %0, %%cluster_ctarank;" : "=r"(r)); return r;
}
__device__ __forceinline__ uint32_t mapa_u32(uint32_t laddr, uint32_t rank) {
    uint32_t r;
    asm("mapa.shared::cluster.u32 %0, %1, %2;" : "=r"(r) : "r"(laddr), "r"(rank));
    return r;
}
__device__ __forceinline__ void cluster_sync_() {
    asm volatile("barrier.cluster.arrive.aligned;" ::: "memory");
    asm volatile("barrier.cluster.wait.aligned;" ::: "memory");
}
__device__ __forceinline__ void bar_sync_(int id, int cnt) {
    asm volatile("bar.sync %0, %1;" :: "r"(id), "r"(cnt) : "memory");
}
__device__ __forceinline__ void mbar_init(uint32_t addr, uint32_t cnt) {
    asm volatile("mbarrier.init.shared.b64 [%0], %1;" :: "r"(addr), "r"(cnt) : "memory");
}
__device__ __forceinline__ void mbar_expect_tx(uint32_t addr, uint32_t bytes) {
    asm volatile("mbarrier.arrive.expect_tx.shared.b64 _, [%0], %1;"
                 :: "r"(addr), "r"(bytes) : "memory");
}
__device__ __forceinline__ void mbar_wait(uint32_t addr, uint32_t parity) {
    asm volatile(
        "{\n\t.reg .pred P;\n\t"
        "WL_%=:\n\t"
        "mbarrier.try_wait.parity.acquire.cluster.shared::cta.b64 P, [%0], %1, 0x989680;\n\t"
        "@!P bra WL_%=;\n\t}"
        :: "r"(addr), "r"(parity) : "memory");
}
// async store to remote cluster smem; signals complete_tx (4 bytes) on remote mbarrier
__device__ __forceinline__ void st_async_f32(uint32_t raddr, float v, uint32_t rmbar) {
    asm volatile("st.async.shared::cluster.mbarrier::complete_tx::bytes.u32 [%0], %1, [%2];"
                 :: "r"(raddr), "r"(__float_as_uint(v)), "r"(rmbar) : "memory");
}
// 16B vector load from shared (LDS.128) into two u64
__device__ __forceinline__ void lds128(unsigned long long& x, unsigned long long& y, uint32_t addr) {
    asm volatile("ld.shared.v2.u64 {%0, %1}, [%2];" : "=l"(x), "=l"(y) : "r"(addr));
}
// packed fp32x2 FMA: d = a*b + d  (sm_100 FFMA2)
__device__ __forceinline__ void fma2(unsigned long long& d, unsigned long long a, unsigned long long b) {
    asm("fma.rn.f32x2 %0, %1, %2, %0;" : "+l"(d) : "l"(a), "l"(b));
}
__device__ __forceinline__ float2 unpack2(unsigned long long v) {
    float2 r; asm("mov.b64 {%0, %1}, %2;" : "=f"(r.x), "=f"(r.y) : "l"(v)); return r;
}
__device__ __forceinline__ unsigned long long pack2(float x, float y) {
    unsigned long long v; asm("mov.b64 %0, {%1, %2};" : "=l"(v) : "f"(x), "f"(y)); return v;
}

// ---------------- prep ----------------
__global__ void prep_kernel(const float* __restrict__ W_in, const float* __restrict__ W_ih,
                            const float* __restrict__ b_ih, const float* __restrict__ b_hh,
                            const float* __restrict__ W_k) {
    int idx = blockIdx.x * blockDim.x + threadIdx.x;
    if (idx < G4 * FDIM) {
        int n = idx / FDIM, k = idx % FDIM;
        g_Wx[idx] = W_ih[n * (FDIM + 1) + k];
    }
    if (idx < DIN * FDIM) {
        int k = idx / FDIM, n = idx % FDIM;
        g_WinT[n * DIN + k] = W_in[idx];
    }
    if (idx < G4) {
        g_wy[idx]   = W_ih[idx * (FDIM + 1) + FDIM];
        g_bsum[idx] = b_ih[idx] + b_hh[idx];
    }
    if (idx < KDIM * HID) {
        int k = idx / HID, h = idx % HID;
        g_WkT[idx] = W_k[h * KDIM + k];
    }
}

// ---------------- GEMM C = A * B^T ----------------
__device__ __forceinline__ void gemm_nt_body(
    const float* __restrict__ A, const float* __restrict__ B, float* __restrict__ C,
    int M, int N, int K,
    const float* __restrict__ bias, const float* __restrict__ yvec, const float* __restrict__ wy)
{
    __shared__ __align__(16) float As[16][64];
    __shared__ __align__(16) float Bs[16][64];
    const int m0 = blockIdx.y * 64, n0 = blockIdx.x * 64;
    const int tid = threadIdx.x;
    const int tx = tid % 16, ty = tid / 16;
    const int lr = tid / 4, lc4 = (tid % 4) * 4;

    float acc[4][4];
#pragma unroll
    for (int i = 0; i < 4; i++)
#pragma unroll
        for (int j = 0; j < 4; j++) acc[i][j] = 0.f;

    for (int k0 = 0; k0 < K; k0 += 16) {
        float4 av = *reinterpret_cast<const float4*>(A + (size_t)(m0 + lr) * K + k0 + lc4);
        As[lc4 + 0][lr] = av.x; As[lc4 + 1][lr] = av.y;
        As[lc4 + 2][lr] = av.z; As[lc4 + 3][lr] = av.w;
        float4 bv = make_float4(0.f, 0.f, 0.f, 0.f);
        if (n0 + lr < N) bv = *reinterpret_cast<const float4*>(B + (size_t)(n0 + lr) * K + k0 + lc4);
        Bs[lc4 + 0][lr] = bv.x; Bs[lc4 + 1][lr] = bv.y;
        Bs[lc4 + 2][lr] = bv.z; Bs[lc4 + 3][lr] = bv.w;
        __syncthreads();
#pragma unroll
        for (int kk = 0; kk < 16; kk++) {
            float4 a4 = *reinterpret_cast<const float4*>(&As[kk][ty * 4]);
            float4 b4 = *reinterpret_cast<const float4*>(&Bs[kk][tx * 4]);
            float aa[4] = {a4.x, a4.y, a4.z, a4.w};
            float bb[4] = {b4.x, b4.y, b4.z, b4.w};
#pragma unroll
            for (int i = 0; i < 4; i++)
#pragma unroll
                for (int j = 0; j < 4; j++) acc[i][j] = fmaf(aa[i], bb[j], acc[i][j]);
        }
        __syncthreads();
    }
#pragma unroll
    for (int i = 0; i < 4; i++) {
        int m = m0 + ty * 4 + i;
        float yv = 0.f;
        if (yvec) yv = (m == 0) ? 0.f : yvec[m - 1];
#pragma unroll
        for (int j = 0; j < 4; j++) {
            int n = n0 + tx * 4 + j;
            if (n < N) {
                float v = acc[i][j] + (bias ? bias[n] : 0.f);
                if (wy) v = fmaf(yv, wy[n], v);
                C[(size_t)m * N + n] = v;
            }
        }
    }
}

__global__ void __launch_bounds__(256) gemm1_kernel(const float* __restrict__ x,
                                                    const float* __restrict__ b_in) {
    gemm_nt_body(x, g_WinT, g_xs, TSTEPS, FDIM, DIN, b_in, nullptr, nullptr);
}
__global__ void __launch_bounds__(256) gemm2_kernel(const float* __restrict__ y) {
    gemm_nt_body(g_xs, g_Wx, g_gx, TSTEPS, G4, FDIM, g_bsum, y, g_wy);
}

// ---------------- fused kernel shared state ----------------
struct Shm {
    __align__(16) float h[4][HID];          // ring of 4 h-buffers (st.async targets)
    __align__(16) float dmy[4];             // consumer dummy landing slots
    __align__(8)  unsigned long long mbar[4];  // tx-counting barriers, one per buffer
    __align__(8)  float Ws[HID];
    __align__(8)  float bk[KDIM];
    __align__(16) float key[2][KDIM];       // double-buffered (keys pipeline vs MANN)
    __align__(16) float kn[2][KDIM];
    float sig[2];
    float wsum[4];
    float bs;
};

// MANN step on buffer kb (threads 0..127 only; uses named barrier 1)
__device__ __forceinline__ void mann_step(Shm& S, int tid, int kb,
                                          unsigned long long* M2, float& wr)
{
    const float sg = S.sig[kb];
    const float ww = fmaf(sg, wr, 1.f - sg);        // wlu mask == 1 identically
    const unsigned long long ww2 = pack2(ww, ww);
    const uint32_t kaddr  = smem_u32(&S.key[kb][0]);
    const uint32_t knaddr = smem_u32(&S.kn[kb][0]);
    unsigned long long n0 = 0, n1 = 0, d0 = 0, d1 = 0;
#pragma unroll
    for (int q = 0; q < 20; q += 2) {
        unsigned long long k0, k1, kn0, kn1;
        lds128(k0,  k1,  kaddr  + (uint32_t)q * 8u);
        lds128(kn0, kn1, knaddr + (uint32_t)q * 8u);
        fma2(M2[q],     ww2, k0);
        fma2(M2[q + 1], ww2, k1);
        fma2(n0, M2[q],     M2[q]);
        fma2(n1, M2[q + 1], M2[q + 1]);
        fma2(d0, M2[q],     kn0);
        fma2(d1, M2[q + 1], kn1);
    }
    float2 na = unpack2(n0), nb = unpack2(n1), da = unpack2(d0), db = unpack2(d1);
    float ns  = (na.x + na.y) + (nb.x + nb.y);      // >= 4e-11, never 0
    float dot = (da.x + da.y) + (db.x + db.y);
    float e = __expf(dot * rsqrtf(ns));             // |logit| <= sqrt(40)
    float acc = e;
#pragma unroll
    for (int off = 16; off > 0; off >>= 1) acc += __shfl_xor_sync(0xffffffffu, acc, off);
    if ((tid & 31) == 0) S.wsum[tid >> 5] = acc;
    bar_sync_(1, 128);                              // MANN group only
    float tot = (S.wsum[0] + S.wsum[1]) + (S.wsum[2] + S.wsum[3]);
    wr = __fdividef(e, tot);
}

// keys + sigma from hidden vector hb into buffer kb (threads 128..215)
__device__ __forceinline__ void keys_sigma(Shm& S, int tid, const float* __restrict__ hb, int kb,
                                           const unsigned long long* wk)
{
    if (tid < 208) {                 // keys: 2 threads per output (tid 128..207)
        const int k = (tid - 128) >> 1, half = (tid - 128) & 1;
        const unsigned mask = (tid < 192) ? 0xffffffffu : 0x0000FFFFu;
        const uint32_t haddr = smem_u32(hb) + (uint32_t)half * 400u;
        unsigned long long a0 = 0, a1 = 0, a2 = 0, a3 = 0;
#pragma unroll
        for (int q = 0; q < 25; q++) {
            unsigned long long x, y;
            lds128(x, y, haddr + (uint32_t)q * 16u);
            if (q & 1) { fma2(a2, wk[2 * q], x); fma2(a3, wk[2 * q + 1], y); }
            else       { fma2(a0, wk[2 * q], x); fma2(a1, wk[2 * q + 1], y); }
        }
        float2 xa = unpack2(a0), xb = unpack2(a1), xc = unpack2(a2), xd = unpack2(a3);
        float acc = ((xa.x + xa.y) + (xb.x + xb.y)) + ((xc.x + xc.y) + (xd.x + xd.y));
        acc += __shfl_xor_sync(mask, acc, 1);
        if (half == 0) {
            float kv = ftanh(acc + S.bk[k]);        // precise path (feeds output M)
            S.key[kb][k] = kv;
            S.kn[kb][k]  = kv / fmaxf(fabsf(kv), EPSF);
        }
    } else if (tid < 216) {          // sigma: 8 threads (warp 6 lanes 16..23)
        const int p = tid - 208;
        float a = 0.f;
#pragma unroll
        for (int i = 0; i < 25; i++) a = fmaf(hb[p * 25 + i], S.Ws[p * 25 + i], a);
        a += __shfl_xor_sync(0x00FF0000u, a, 4);
        a += __shfl_xor_sync(0x00FF0000u, a, 2);
        a += __shfl_xor_sync(0x00FF0000u, a, 1);
        if (p == 0) S.sig[kb] = fsigmoid(a + S.bs);
    }
}

__global__ void __cluster_dims__(CLSZ, 1, 1) __launch_bounds__(256, 1)
fused_kernel(const float* __restrict__ W_hh,
             const float* __restrict__ b_k,
             const float* __restrict__ W_s, const float* __restrict__ b_s,
             float* __restrict__ out)
{
    __shared__ Shm S;
    const int tid = threadIdx.x;
    const uint32_t rank = my_cluster_rank();
    const bool is_consumer = (rank == CLSZ - 1);

    const uint32_t mbarA = smem_u32(&S.mbar[0]);
    const uint32_t hA    = smem_u32(&S.h[0][0]);
    const uint32_t dmyA  = smem_u32(&S.dmy[0]);

    if (tid < HID) S.h[0][tid] = 0.f;     // h_0 = 0 (buf 1..3 fully written before read)
    if (tid == 0) {
#pragma unroll
        for (int i = 0; i < 4; i++) {
            mbar_init(mbarA + 8u * i, 1);          // 1 arrival/phase (the expect_tx)
            mbar_expect_tx(mbarA + 8u * i, TXB);   // arm phase 0
        }
    }

    // ---------- producer init (R15-identical partition) ----------
    const int units = is_consumer ? 0 : ((rank < 6) ? 29 : 26);
    const int base  = 29 * (int)rank;            // rank 6 -> 174
    const int nact  = 8 * units;
    const bool act  = tid < nact;
    const int u   = tid >> 3;
    const int sub = tid & 7;                     // 2*gate + cc
    const int g   = sub >> 1;
    const int cc  = sub & 1;
    const int grow = act ? (g * HID + base + u) : 0;

    unsigned long long w[50];
    if (act) {
        const unsigned long long* wp =
            reinterpret_cast<const unsigned long long*>(W_hh + (size_t)grow * HID + cc * 100);
#pragma unroll
        for (int q = 0; q < 50; q++) w[q] = wp[q];
    }
    unsigned mask = 0;
    if (act) {
        int rem = nact - (tid & ~31);
        mask = (rem >= 32) ? 0xffffffffu : ((1u << rem) - 1u);
    }
    uint32_t r_h[CLSZ], r_mb[CLSZ];
    if ((act && sub == 0) || (is_consumer && tid < CLSZ)) {
#pragma unroll
        for (int p = 0; p < CLSZ; p++) {
            r_h[p]  = mapa_u32(hA,    (uint32_t)p);
            r_mb[p] = mapa_u32(mbarA, (uint32_t)p);
        }
    }

    // ---------- consumer init ----------
    unsigned long long wk[50];
    unsigned long long M2[20];
    float wr = 0.f;
    if (is_consumer) {
        if (tid >= 128 && tid < 208) {
            const int k = (tid - 128) >> 1, half = (tid - 128) & 1;
            const unsigned long long* wp =
                reinterpret_cast<const unsigned long long*>(g_WkT + k * HID + half * 100);
#pragma unroll
            for (int q = 0; q < 50; q++) wk[q] = wp[q];
        }
        for (int i = tid; i < HID; i += 256) S.Ws[i] = W_s[i];
        if (tid < KDIM) S.bk[tid] = b_k[tid];
        if (tid == 0)   S.bs = b_s[0];
        if (tid < NSLOT) {
#pragma unroll
            for (int q = 0; q < 20; q++) M2[q] = pack2(1e-6f, 1e-6f);
            wr = (tid == 0) ? 1.f : 0.f;
        }
    }

    __syncthreads();
    cluster_sync_();   // barriers armed + h_0 zeroed everywhere before any st.async

    unsigned par4 = 0;   // per-barrier wait parity (bit i = mbar[i]); toggled on each wait

    if (!is_consumer) {
        // ================= LSTM producer =================
        float cst = 0.f;
        float gxv = (act && cc == 0) ? g_gx[grow] : 0.f;

        for (int t = 0; t < TSTEPS; t++) {
            const int rb = t & 3;                 // read buffer (h_t), barrier index
            const int wb = (t + 1) & 3;           // write buffer (h_{t+1})
            float gxn = 0.f;
            if (act && cc == 0) {                 // prefetch flies during the wait
                int tn = (t + 1 < TSTEPS) ? (t + 1) : t;
                gxn = g_gx[(size_t)tn * G4 + grow];
            }
            if (t >= 1) {                         // h_t delivered: 800B + consumer dummy
                mbar_wait(mbarA + 8u * rb, (par4 >> rb) & 1u);
                par4 ^= 1u << rb;
                if (tid == 0) mbar_expect_tx(mbarA + 8u * rb, TXB);   // re-arm next phase
            }
            if (act) {
                const uint32_t haddr = smem_u32(&S.h[rb][0]) + (uint32_t)cc * 400u;
                unsigned long long a0 = 0, a1 = 0, a2 = 0, a3 = 0;
#pragma unroll
                for (int q = 0; q < 25; q++) {
                    unsigned long long x, y;
                    lds128(x, y, haddr + (uint32_t)q * 16u);
                    if (q & 1) { fma2(a2, w[2 * q], x); fma2(a3, w[2 * q + 1], y); }
                    else       { fma2(a0, w[2 * q], x); fma2(a1, w[2 * q + 1], y); }
                }
                float2 f0 = unpack2(a0), f1 = unpack2(a1), f2 = unpack2(a2), f3 = unpack2(a3);
                float dsum = ((f0.x + f0.y) + (f1.x + f1.y)) + ((f2.x + f2.y) + (f3.x + f3.y));
                dsum += __shfl_xor_sync(mask, dsum, 1);          // combine k-halves
                float av = 0.f;
                if (cc == 0) {
                    float gs = dsum + gxv;
                    av = (g == 2) ? tanh_ap(gs) : sig_ap(gs);    // MUFU.TANH fast gates
                }
                float fv = __shfl_down_sync(mask, av, 2);
                float gv = __shfl_down_sync(mask, av, 4);
                float ov = __shfl_down_sync(mask, av, 6);
                if (sub == 0) {
                    cst = fv * cst + av * gv;
                    float h = ov * tanh_ap(cst);
                    const uint32_t off = (uint32_t)(wb * HID + base + u) * 4u;
                    const uint32_t mbo = 8u * (uint32_t)wb;
                    if (t + 1 < TSTEPS) {
#pragma unroll
                        for (int p = 0; p < CLSZ; p++)
                            st_async_f32(r_h[p] + off, h, r_mb[p] + mbo);
                    } else {
                        // last step: only the consumer still waits on h_T
                        st_async_f32(r_h[CLSZ - 1] + off, h, r_mb[CLSZ - 1] + mbo);
                    }
                }
            }
            gxv = gxn;
            __syncthreads();   // bound intra-CTA warp drift to <1 step (buffer reuse safety)
        }
        cluster_sync_();       // keep smem alive for any in-flight remote ops
        return;
    }

    // ================= consumer: keys + sigma + MANN =================
    // prologue dummy: completes every rank's mbar[1] to TXB for step/state s=1
    if (tid < CLSZ) st_async_f32(r_h[tid] /*scratch*/ - 0 + (smem_u32(&S.dmy[1]) - hA), 0.f,
                                 r_mb[tid] + 8u * 1u);

    for (int s = 1; s <= TSTEPS; s++) {
        const int rb = s & 3;
        mbar_wait(mbarA + 8u * rb, (par4 >> rb) & 1u);   // h_s delivered to our smem
        par4 ^= 1u << rb;
        if (tid == 0) mbar_expect_tx(mbarA + 8u * rb, TXB);

        // keys(h_s) on warps 4-7 || MANN(s-1) on warps 0-3
        if (tid >= 128) {
            keys_sigma(S, tid, &S.h[rb][0], s & 1, wk);
        } else if (s >= 2) {
            mann_step(S, tid, (s - 1) & 1, M2, wr);
        }
        __syncthreads();   // all reads of h[rb] + key double-buffer ordering

        // done-with-h_s dummy -> mbar[(s+1)&3]: producers need it for t=s+1 (<=4095),
        // we need our own for s+1 (<=4096). Send only to ranks that will consume it.
        if (tid < CLSZ) {
            const int nb = (s + 1) & 3;
            const uint32_t doff = (smem_u32(&S.dmy[nb]) - hA);
            if (s + 1 <= TSTEPS - 1) {
                st_async_f32(r_h[tid] + doff, 0.f, r_mb[tid] + 8u * (uint32_t)nb);
            } else if (s + 1 == TSTEPS && tid == CLSZ - 1) {
                st_async_f32(r_h[tid] + doff, 0.f, r_mb[tid] + 8u * (uint32_t)nb);
            }
        }
    }

    // tail: MANN for keys(s=4096) (kb = 4096&1 = 0)
    if (tid < 128) mann_step(S, tid, 0, M2, wr);

    if (tid < NSLOT) {
#pragma unroll
        for (int q = 0; q < 20; q++) {
            float2 v = unpack2(M2[q]);
            out[tid * KDIM + 2 * q]     = v.x;
            out[tid * KDIM + 2 * q + 1] = v.y;
        }
    }
    cluster_sync_();       // keep smem alive for any in-flight remote ops
}

// ---------------- launch ----------------
extern "C" void kernel_launch(void* const* d_in, const int* in_sizes, int n_in,
                              void* d_out, int out_size) {
    const float* x    = (const float*)d_in[0];
    const float* y    = (const float*)d_in[1];
    const float* W_in = (const float*)d_in[2];
    const float* b_in = (const float*)d_in[3];
    const float* W_ih = (const float*)d_in[4];
    const float* W_hh = (const float*)d_in[5];
    const float* b_ih = (const float*)d_in[6];
    const float* b_hh = (const float*)d_in[7];
    const float* W_k  = (const float*)d_in[8];
    const float* b_k  = (const float*)d_in[9];
    const float* W_s  = (const float*)d_in[10];
    const float* b_s  = (const float*)d_in[11];
    // gamma (d_in[12]) provably unused: wlu mask is identically 1, wu/gamma cancel

    prep_kernel<<<(G4 * FDIM + 255) / 256, 256>>>(W_in, W_ih, b_ih, b_hh, W_k);
    gemm1_kernel<<<dim3(FDIM / 64, TSTEPS / 64), 256>>>(x, b_in);
    gemm2_kernel<<<dim3((G4 + 63) / 64, TSTEPS / 64), 256>>>(y);
    fused_kernel<<<CLSZ, 256>>>(W_hh, b_k, W_s, b_s, (float*)d_out);
}

// round 17
// speedup vs baseline: 1.5295x; 1.0570x over previous
#include <cuda_runtime.h>
#include <cstdint>
#include <math.h>

#define TSTEPS 4096
#define DIN    512
#define FDIM   256
#define HID    200
#define G4     800
#define KDIM   40
#define NSLOT  128
#define EPSF   1e-12f
#define CLSZ   8
#define TXB    804u    // 800B h-data + 4B consumer dummy, every barrier every phase

// ---------------- scratch (device globals) ----------------
__device__ float g_xs[TSTEPS * FDIM];
__device__ float g_gx[TSTEPS * G4];
__device__ float g_WinT[FDIM * DIN];
__device__ float g_Wx[G4 * FDIM];
__device__ float g_wy[G4];
__device__ float g_bsum[G4];
__device__ float g_WkT[KDIM * HID];   // W_k transposed: [40][200]

// ---------------- helpers ----------------
__device__ __forceinline__ float fsigmoid(float x) {
    return __fdividef(1.f, 1.f + __expf(-x));
}
__device__ __forceinline__ float ftanh(float x) {
    float a = fabsf(x);
    float e = __expf(-2.f * a);
    float r = __fdividef(1.f - e, 1.f + e);
    return copysignf(r, x);
}
// hardware tanh (MUFU.TANH): 1 op, max err ~2^-11 — producer gates only
__device__ __forceinline__ float tanh_ap(float x) {
    float r; asm("tanh.approx.f32 %0, %1;" : "=f"(r) : "f"(x)); return r;
}
__device__ __forceinline__ float sig_ap(float x) {
    return fmaf(tanh_ap(0.5f * x), 0.5f, 0.5f);
}
__device__ __forceinline__ uint32_t smem_u32(const void* p) {
    return (uint32_t)__cvta_generic_to_shared(p);
}
__device__ __forceinline__ uint32_t my_cluster_rank() {
    uint32_t r; asm("mov.u32 %0, %%cluster_ctarank;" : "=r"(r)); return r;
}
__device__ __forceinline__ uint32_t mapa_u32(uint32_t laddr, uint32_t rank) {
    uint32_t r;
    asm("mapa.shared::cluster.u32 %0, %1, %2;" : "=r"(r) : "r"(laddr), "r"(rank));
    return r;
}
__device__ __forceinline__ void cluster_sync_() {
    asm volatile("barrier.cluster.arrive.aligned;" ::: "memory");
    asm volatile("barrier.cluster.wait.aligned;" ::: "memory");
}
__device__ __forceinline__ void bar_sync_(int id, int cnt) {
    asm volatile("bar.sync %0, %1;" :: "r"(id), "r"(cnt) : "memory");
}
__device__ __forceinline__ void mbar_init(uint32_t addr, uint32_t cnt) {
    asm volatile("mbarrier.init.shared.b64 [%0], %1;" :: "r"(addr), "r"(cnt) : "memory");
}
__device__ __forceinline__ void mbar_expect_tx(uint32_t addr, uint32_t bytes) {
    asm volatile("mbarrier.arrive.expect_tx.shared.b64 _, [%0], %1;"
                 :: "r"(addr), "r"(bytes) : "memory");
}
__device__ __forceinline__ void mbar_wait(uint32_t addr, uint32_t parity) {
    asm volatile(
        "{\n\t.reg .pred P;\n\t"
        "WL_%=:\n\t"
        "mbarrier.try_wait.parity.acquire.cluster.shared::cta.b64 P, [%0], %1, 0x989680;\n\t"
        "@!P bra WL_%=;\n\t}"
        :: "r"(addr), "r"(parity) : "memory");
}
// async store to remote cluster smem; signals complete_tx (4 bytes) on remote mbarrier
__device__ __forceinline__ void st_async_f32(uint32_t raddr, float v, uint32_t rmbar) {
    asm volatile("st.async.shared::cluster.mbarrier::complete_tx::bytes.u32 [%0], %1, [%2];"
                 :: "r"(raddr), "r"(__float_as_uint(v)), "r"(rmbar) : "memory");
}
// 16B vector load from shared (LDS.128) into two u64
__device__ __forceinline__ void lds128(unsigned long long& x, unsigned long long& y, uint32_t addr) {
    asm volatile("ld.shared.v2.u64 {%0, %1}, [%2];" : "=l"(x), "=l"(y) : "r"(addr));
}
// packed fp32x2 FMA: d = a*b + d  (sm_100 FFMA2)
__device__ __forceinline__ void fma2(unsigned long long& d, unsigned long long a, unsigned long long b) {
    asm("fma.rn.f32x2 %0, %1, %2, %0;" : "+l"(d) : "l"(a), "l"(b));
}
__device__ __forceinline__ float2 unpack2(unsigned long long v) {
    float2 r; asm("mov.b64 {%0, %1}, %2;" : "=f"(r.x), "=f"(r.y) : "l"(v)); return r;
}
__device__ __forceinline__ unsigned long long pack2(float x, float y) {
    unsigned long long v; asm("mov.b64 %0, {%1, %2};" : "=l"(v) : "f"(x), "f"(y)); return v;
}

// ---------------- prep ----------------
__global__ void prep_kernel(const float* __restrict__ W_in, const float* __restrict__ W_ih,
                            const float* __restrict__ b_ih, const float* __restrict__ b_hh,
                            const float* __restrict__ W_k) {
    int idx = blockIdx.x * blockDim.x + threadIdx.x;
    if (idx < G4 * FDIM) {
        int n = idx / FDIM, k = idx % FDIM;
        g_Wx[idx] = W_ih[n * (FDIM + 1) + k];
    }
    if (idx < DIN * FDIM) {
        int k = idx / FDIM, n = idx % FDIM;
        g_WinT[n * DIN + k] = W_in[idx];
    }
    if (idx < G4) {
        g_wy[idx]   = W_ih[idx * (FDIM + 1) + FDIM];
        g_bsum[idx] = b_ih[idx] + b_hh[idx];
    }
    if (idx < KDIM * HID) {
        int k = idx / HID, h = idx % HID;
        g_WkT[idx] = W_k[h * KDIM + k];
    }
}

// ---------------- GEMM C = A * B^T ----------------
__device__ __forceinline__ void gemm_nt_body(
    const float* __restrict__ A, const float* __restrict__ B, float* __restrict__ C,
    int M, int N, int K,
    const float* __restrict__ bias, const float* __restrict__ yvec, const float* __restrict__ wy)
{
    __shared__ __align__(16) float As[16][64];
    __shared__ __align__(16) float Bs[16][64];
    const int m0 = blockIdx.y * 64, n0 = blockIdx.x * 64;
    const int tid = threadIdx.x;
    const int tx = tid % 16, ty = tid / 16;
    const int lr = tid / 4, lc4 = (tid % 4) * 4;

    float acc[4][4];
#pragma unroll
    for (int i = 0; i < 4; i++)
#pragma unroll
        for (int j = 0; j < 4; j++) acc[i][j] = 0.f;

    for (int k0 = 0; k0 < K; k0 += 16) {
        float4 av = *reinterpret_cast<const float4*>(A + (size_t)(m0 + lr) * K + k0 + lc4);
        As[lc4 + 0][lr] = av.x; As[lc4 + 1][lr] = av.y;
        As[lc4 + 2][lr] = av.z; As[lc4 + 3][lr] = av.w;
        float4 bv = make_float4(0.f, 0.f, 0.f, 0.f);
        if (n0 + lr < N) bv = *reinterpret_cast<const float4*>(B + (size_t)(n0 + lr) * K + k0 + lc4);
        Bs[lc4 + 0][lr] = bv.x; Bs[lc4 + 1][lr] = bv.y;
        Bs[lc4 + 2][lr] = bv.z; Bs[lc4 + 3][lr] = bv.w;
        __syncthreads();
#pragma unroll
        for (int kk = 0; kk < 16; kk++) {
            float4 a4 = *reinterpret_cast<const float4*>(&As[kk][ty * 4]);
            float4 b4 = *reinterpret_cast<const float4*>(&Bs[kk][tx * 4]);
            float aa[4] = {a4.x, a4.y, a4.z, a4.w};
            float bb[4] = {b4.x, b4.y, b4.z, b4.w};
#pragma unroll
            for (int i = 0; i < 4; i++)
#pragma unroll
                for (int j = 0; j < 4; j++) acc[i][j] = fmaf(aa[i], bb[j], acc[i][j]);
        }
        __syncthreads();
    }
#pragma unroll
    for (int i = 0; i < 4; i++) {
        int m = m0 + ty * 4 + i;
        float yv = 0.f;
        if (yvec) yv = (m == 0) ? 0.f : yvec[m - 1];
#pragma unroll
        for (int j = 0; j < 4; j++) {
            int n = n0 + tx * 4 + j;
            if (n < N) {
                float v = acc[i][j] + (bias ? bias[n] : 0.f);
                if (wy) v = fmaf(yv, wy[n], v);
                C[(size_t)m * N + n] = v;
            }
        }
    }
}

__global__ void __launch_bounds__(256) gemm1_kernel(const float* __restrict__ x,
                                                    const float* __restrict__ b_in) {
    gemm_nt_body(x, g_WinT, g_xs, TSTEPS, FDIM, DIN, b_in, nullptr, nullptr);
}
__global__ void __launch_bounds__(256) gemm2_kernel(const float* __restrict__ y) {
    gemm_nt_body(g_xs, g_Wx, g_gx, TSTEPS, G4, FDIM, g_bsum, y, g_wy);
}

// ---------------- fused kernel shared state ----------------
struct Shm {
    __align__(16) float h[4][HID];          // ring of 4 h-buffers (st.async targets)
    __align__(16) float dmy[4];             // consumer dummy landing slots
    __align__(8)  unsigned long long mbar[4];  // tx-counting barriers, one per buffer
    __align__(8)  float Ws[HID];
    __align__(8)  float bk[KDIM];
    __align__(16) float key[2][KDIM];       // double-buffered (keys pipeline vs MANN)
    __align__(16) float kn[2][KDIM];
    float sig[2];
    float wsum[4];
    float bs;
};

// MANN step on buffer kb (threads 0..127 only; uses named barrier 1)
__device__ __forceinline__ void mann_step(Shm& S, int tid, int kb,
                                          unsigned long long* M2, float& wr)
{
    const float sg = S.sig[kb];
    const float ww = fmaf(sg, wr, 1.f - sg);        // wlu mask == 1 identically
    const unsigned long long ww2 = pack2(ww, ww);
    const uint32_t kaddr  = smem_u32(&S.key[kb][0]);
    const uint32_t knaddr = smem_u32(&S.kn[kb][0]);
    unsigned long long n0 = 0, n1 = 0, d0 = 0, d1 = 0;
#pragma unroll
    for (int q = 0; q < 20; q += 2) {
        unsigned long long k0, k1, kn0, kn1;
        lds128(k0,  k1,  kaddr  + (uint32_t)q * 8u);
        lds128(kn0, kn1, knaddr + (uint32_t)q * 8u);
        fma2(M2[q],     ww2, k0);
        fma2(M2[q + 1], ww2, k1);
        fma2(n0, M2[q],     M2[q]);
        fma2(n1, M2[q + 1], M2[q + 1]);
        fma2(d0, M2[q],     kn0);
        fma2(d1, M2[q + 1], kn1);
    }
    float2 na = unpack2(n0), nb = unpack2(n1), da = unpack2(d0), db = unpack2(d1);
    float ns  = (na.x + na.y) + (nb.x + nb.y);      // >= 4e-11, never 0
    float dot = (da.x + da.y) + (db.x + db.y);
    float e = __expf(dot * rsqrtf(ns));             // |logit| <= sqrt(40)
    float acc = e;
#pragma unroll
    for (int off = 16; off > 0; off >>= 1) acc += __shfl_xor_sync(0xffffffffu, acc, off);
    if ((tid & 31) == 0) S.wsum[tid >> 5] = acc;
    bar_sync_(1, 128);                              // MANN group only
    float tot = (S.wsum[0] + S.wsum[1]) + (S.wsum[2] + S.wsum[3]);
    wr = __fdividef(e, tot);
}

// keys + sigma from hidden vector hb into buffer kb (threads 128..215)
__device__ __forceinline__ void keys_sigma(Shm& S, int tid, const float* __restrict__ hb, int kb,
                                           const unsigned long long* wk)
{
    if (tid < 208) {                 // keys: 2 threads per output (tid 128..207)
        const int k = (tid - 128) >> 1, half = (tid - 128) & 1;
        const unsigned mask = (tid < 192) ? 0xffffffffu : 0x0000FFFFu;
        const uint32_t haddr = smem_u32(hb) + (uint32_t)half * 400u;
        unsigned long long a0 = 0, a1 = 0, a2 = 0, a3 = 0;
#pragma unroll
        for (int q = 0; q < 25; q++) {
            unsigned long long x, y;
            lds128(x, y, haddr + (uint32_t)q * 16u);
            if (q & 1) { fma2(a2, wk[2 * q], x); fma2(a3, wk[2 * q + 1], y); }
            else       { fma2(a0, wk[2 * q], x); fma2(a1, wk[2 * q + 1], y); }
        }
        float2 xa = unpack2(a0), xb = unpack2(a1), xc = unpack2(a2), xd = unpack2(a3);
        float acc = ((xa.x + xa.y) + (xb.x + xb.y)) + ((xc.x + xc.y) + (xd.x + xd.y));
        acc += __shfl_xor_sync(mask, acc, 1);
        if (half == 0) {
            float kv = ftanh(acc + S.bk[k]);        // precise path (feeds output M)
            S.key[kb][k] = kv;
            S.kn[kb][k]  = kv / fmaxf(fabsf(kv), EPSF);
        }
    } else if (tid < 216) {          // sigma: 8 threads (warp 6 lanes 16..23)
        const int p = tid - 208;
        float a = 0.f;
#pragma unroll
        for (int i = 0; i < 25; i++) a = fmaf(hb[p * 25 + i], S.Ws[p * 25 + i], a);
        a += __shfl_xor_sync(0x00FF0000u, a, 4);
        a += __shfl_xor_sync(0x00FF0000u, a, 2);
        a += __shfl_xor_sync(0x00FF0000u, a, 1);
        if (p == 0) S.sig[kb] = fsigmoid(a + S.bs);
    }
}

__global__ void __cluster_dims__(CLSZ, 1, 1) __launch_bounds__(256, 1)
fused_kernel(const float* __restrict__ W_hh,
             const float* __restrict__ b_k,
             const float* __restrict__ W_s, const float* __restrict__ b_s,
             float* __restrict__ out)
{
    __shared__ Shm S;
    const int tid = threadIdx.x;
    const uint32_t rank = my_cluster_rank();
    const bool is_consumer = (rank == CLSZ - 1);

    const uint32_t mbarA = smem_u32(&S.mbar[0]);
    const uint32_t hA    = smem_u32(&S.h[0][0]);
    const uint32_t dmyA  = smem_u32(&S.dmy[0]);

    if (tid < HID) S.h[0][tid] = 0.f;     // h_0 = 0 (buf 1..3 fully written before read)
    if (tid == 0) {
#pragma unroll
        for (int i = 0; i < 4; i++) {
            mbar_init(mbarA + 8u * i, 1);          // 1 arrival/phase (the expect_tx)
            mbar_expect_tx(mbarA + 8u * i, TXB);   // arm phase 0
        }
    }

    // ---------- producer init ----------
    const int units = is_consumer ? 0 : ((rank < 6) ? 29 : 26);
    const int base  = 29 * (int)rank;            // rank 6 -> 174
    const int nact  = 8 * units;
    const bool act  = tid < nact;
    const int u   = tid >> 3;
    const int sub = tid & 7;                     // 2*gate + cc
    const int g   = sub >> 1;
    const int cc  = sub & 1;
    const int grow = act ? (g * HID + base + u) : 0;

    unsigned long long w[50];
    if (act) {
        const unsigned long long* wp =
            reinterpret_cast<const unsigned long long*>(W_hh + (size_t)grow * HID + cc * 100);
#pragma unroll
        for (int q = 0; q < 50; q++) w[q] = wp[q];
    }
    unsigned mask = 0;
    if (act) {
        int rem = nact - (tid & ~31);
        mask = (rem >= 32) ? 0xffffffffu : ((1u << rem) - 1u);
    }
    uint32_t r_h[CLSZ], r_mb[CLSZ];
    if ((act && sub == 0) || (is_consumer && tid < CLSZ)) {
#pragma unroll
        for (int p = 0; p < CLSZ; p++) {
            r_h[p]  = mapa_u32(hA,    (uint32_t)p);
            r_mb[p] = mapa_u32(mbarA, (uint32_t)p);
        }
    }

    // ---------- consumer init ----------
    unsigned long long wk[50];
    unsigned long long M2[20];
    float wr = 0.f;
    if (is_consumer) {
        if (tid >= 128 && tid < 208) {
            const int k = (tid - 128) >> 1, half = (tid - 128) & 1;
            const unsigned long long* wp =
                reinterpret_cast<const unsigned long long*>(g_WkT + k * HID + half * 100);
#pragma unroll
            for (int q = 0; q < 50; q++) wk[q] = wp[q];
        }
        for (int i = tid; i < HID; i += 256) S.Ws[i] = W_s[i];
        if (tid < KDIM) S.bk[tid] = b_k[tid];
        if (tid == 0)   S.bs = b_s[0];
        if (tid < NSLOT) {
#pragma unroll
            for (int q = 0; q < 20; q++) M2[q] = pack2(1e-6f, 1e-6f);
            wr = (tid == 0) ? 1.f : 0.f;
        }
    }

    __syncthreads();
    cluster_sync_();   // barriers armed + h_0 zeroed everywhere before any st.async

    unsigned par4 = 0;   // per-barrier wait parity (bit i = mbar[i]); toggled on each wait

    if (!is_consumer) {
        // ================= LSTM producer =================
        float cst = 0.f;
        float gxv = (act && cc == 0) ? g_gx[grow] : 0.f;

        for (int t = 0; t < TSTEPS; t++) {
            const int rb = t & 3;                 // read buffer (h_t), barrier index
            const int wb = (t + 1) & 3;           // write buffer (h_{t+1})
            float gxn = 0.f;
            if (act && cc == 0) {                 // prefetch flies during the wait
                int tn = (t + 1 < TSTEPS) ? (t + 1) : t;
                gxn = g_gx[(size_t)tn * G4 + grow];
            }
            if (t >= 1) {                         // h_t delivered: 800B + consumer dummy
                mbar_wait(mbarA + 8u * rb, (par4 >> rb) & 1u);
                par4 ^= 1u << rb;
                if (tid == 0) mbar_expect_tx(mbarA + 8u * rb, TXB);   // re-arm next phase
            }
            if (act) {
                const uint32_t haddr = smem_u32(&S.h[rb][0]) + (uint32_t)cc * 400u;
                unsigned long long a0 = 0, a1 = 0, a2 = 0, a3 = 0;
#pragma unroll
                for (int q = 0; q < 25; q++) {
                    unsigned long long x, y;
                    lds128(x, y, haddr + (uint32_t)q * 16u);
                    if (q & 1) { fma2(a2, w[2 * q], x); fma2(a3, w[2 * q + 1], y); }
                    else       { fma2(a0, w[2 * q], x); fma2(a1, w[2 * q + 1], y); }
                }
                float2 f0 = unpack2(a0), f1 = unpack2(a1), f2 = unpack2(a2), f3 = unpack2(a3);
                float dsum = ((f0.x + f0.y) + (f1.x + f1.y)) + ((f2.x + f2.y) + (f3.x + f3.y));
                dsum += __shfl_xor_sync(mask, dsum, 1);          // combine k-halves
                float av = 0.f;
                if (cc == 0) {
                    float gs = dsum + gxv;
                    av = (g == 2) ? tanh_ap(gs) : sig_ap(gs);    // MUFU.TANH fast gates
                }
                float fv = __shfl_down_sync(mask, av, 2);
                float gv = __shfl_down_sync(mask, av, 4);
                float ov = __shfl_down_sync(mask, av, 6);
                if (sub == 0) {
                    cst = fv * cst + av * gv;
                    float h = ov * tanh_ap(cst);
                    const uint32_t off = (uint32_t)(wb * HID + base + u) * 4u;
                    const uint32_t mbo = 8u * (uint32_t)wb;
                    if (t + 1 < TSTEPS) {
#pragma unroll
                        for (int p = 0; p < CLSZ; p++)
                            st_async_f32(r_h[p] + off, h, r_mb[p] + mbo);
                    } else {
                        // last step: only the consumer still waits on h_T
                        st_async_f32(r_h[CLSZ - 1] + off, h, r_mb[CLSZ - 1] + mbo);
                    }
                }
            }
            gxv = gxn;
            __syncthreads();   // bound intra-CTA warp drift to <1 step (buffer reuse safety)
        }
        cluster_sync_();       // keep smem alive for any in-flight remote ops
        return;
    }

    // ================= consumer: keys + sigma + MANN =================
    // Prologue: pre-seed read-ACK dummies for barriers 1,2,3 (phase 0) at all ranks.
    // These stand in for "consumer done reading h_{-2}, h_{-1}, h_0" — vacuously true.
    if (tid < CLSZ) {
#pragma unroll
        for (int b = 1; b <= 3; b++)
            st_async_f32(r_h[tid] + (dmyA + 4u * (uint32_t)b - hA), 0.f,
                         r_mb[tid] + 8u * (uint32_t)b);
    }

    for (int s = 1; s <= TSTEPS; s++) {
        const int rb = s & 3;
        mbar_wait(mbarA + 8u * rb, (par4 >> rb) & 1u);   // h_s delivered to our smem
        par4 ^= 1u << rb;
        if (tid == 0) mbar_expect_tx(mbarA + 8u * rb, TXB);

        // keys(h_s) on warps 4-7 || MANN(s-1) on warps 0-3
        if (tid >= 128) {
            keys_sigma(S, tid, &S.h[rb][0], s & 1, wk);
        } else if (s >= 2) {
            mann_step(S, tid, (s - 1) & 1, M2, wr);
        }
        __syncthreads();   // all reads of h[rb] + key double-buffer ordering

        // read-ACK for h_s -> barrier (s+3)&3: gates the write of h_{s+4}, which is
        // the first write that overwrites h_s's buffer. ~3 steps of delivery slack,
        // off the per-step critical path. Producers need it for t=s+3 <= 4095
        // (s <= 4092); we need our own for s' = s+3 <= 4096 (s <= 4093).
        if (tid < CLSZ) {
            const int nb = (s + 3) & 3;
            const uint32_t daddr = r_h[tid] + (dmyA + 4u * (uint32_t)nb - hA);
            if (s <= TSTEPS - 4) {
                st_async_f32(daddr, 0.f, r_mb[tid] + 8u * (uint32_t)nb);
            } else if (s == TSTEPS - 3 && tid == CLSZ - 1) {
                st_async_f32(daddr, 0.f, r_mb[tid] + 8u * (uint32_t)nb);
            }
        }
    }

    // tail: MANN for keys(s=4096) (kb = 4096&1 = 0)
    if (tid < 128) mann_step(S, tid, 0, M2, wr);

    if (tid < NSLOT) {
#pragma unroll
        for (int q = 0; q < 20; q++) {
            float2 v = unpack2(M2[q]);
            out[tid * KDIM + 2 * q]     = v.x;
            out[tid * KDIM + 2 * q + 1] = v.y;
        }
    }
    cluster_sync_();       // keep smem alive for any in-flight remote ops
}

// ---------------- launch ----------------
extern "C" void kernel_launch(void* const* d_in, const int* in_sizes, int n_in,
                              void* d_out, int out_size) {
    const float* x    = (const float*)d_in[0];
    const float* y    = (const float*)d_in[1];
    const float* W_in = (const float*)d_in[2];
    const float* b_in = (const float*)d_in[3];
    const float* W_ih = (const float*)d_in[4];
    const float* W_hh = (const float*)d_in[5];
    const float* b_ih = (const float*)d_in[6];
    const float* b_hh = (const float*)d_in[7];
    const float* W_k  = (const float*)d_in[8];
    const float* b_k  = (const float*)d_in[9];
    const float* W_s  = (const float*)d_in[10];
    const float* b_s  = (const float*)d_in[11];
    // gamma (d_in[12]) provably unused: wlu mask is identically 1, wu/gamma cancel

    prep_kernel<<<(G4 * FDIM + 255) / 256, 256>>>(W_in, W_ih, b_ih, b_hh, W_k);
    gemm1_kernel<<<dim3(FDIM / 64, TSTEPS / 64), 256>>>(x, b_in);
    gemm2_kernel<<<dim3((G4 + 63) / 64, TSTEPS / 64), 256>>>(y);
    fused_kernel<<<CLSZ, 256>>>(W_hh, b_k, W_s, b_s, (float*)d_out);
}